// round 4
// baseline (speedup 1.0000x reference)
#include <cuda_runtime.h>
#include <stdint.h>
#include <math.h>

#define BB 4
#define NN_ 1024
#define CC 1024
#define HH 16
#define HD_ 64
#define M_ROWS (BB * NN_)        // 4096
#define QKV_COLS (3 * CC)        // 3072

__device__ float g_qkv[(size_t)M_ROWS * QKV_COLS];   // 48 MB
__device__ float g_ctx[(size_t)M_ROWS * CC];         // 16 MB

// ---------------------------------------------------------------------------
// tf32 helpers
// ---------------------------------------------------------------------------
__device__ __forceinline__ uint32_t f2tf(float f) {
    uint32_t r;
    asm("cvt.rna.tf32.f32 %0, %1;" : "=r"(r) : "f"(f));
    return r;
}

__device__ __forceinline__ void mma8(float* d, const uint32_t* a, const uint32_t* b) {
    asm volatile(
        "mma.sync.aligned.m16n8k8.row.col.f32.tf32.tf32.f32 "
        "{%0,%1,%2,%3}, {%4,%5,%6,%7}, {%8,%9}, {%0,%1,%2,%3};"
        : "+f"(d[0]), "+f"(d[1]), "+f"(d[2]), "+f"(d[3])
        : "r"(a[0]), "r"(a[1]), "r"(a[2]), "r"(a[3]), "r"(b[0]), "r"(b[1]));
}

// ---------------------------------------------------------------------------
// Generic NN GEMM + bias, tf32 MMA. C[M,N] = A[M,K] @ B[K,N] + bias[N]
// Block tile 128x128x16, 256 threads (8 warps, warp tile 32x64).
// ---------------------------------------------------------------------------
__global__ __launch_bounds__(256) void gemm_tf32_bias(
    const float* __restrict__ A, const float* __restrict__ B,
    const float* __restrict__ bias, float* __restrict__ C,
    int M, int N, int K, int lda, int ldb, int ldc) {

    __shared__ uint32_t As[16][136];
    __shared__ uint32_t Bs[16][136];

    const int tid  = threadIdx.x;
    const int lane = tid & 31;
    const int w    = tid >> 5;
    const int wm   = w & 3;
    const int wn   = w >> 2;
    const int row0 = blockIdx.y * 128;
    const int col0 = blockIdx.x * 128;
    const int m_base = wm * 32;
    const int n_base = wn * 64;
    const int lr = lane >> 2;
    const int lc = lane & 3;

    float acc[2][8][4];
#pragma unroll
    for (int i = 0; i < 2; i++)
#pragma unroll
        for (int j = 0; j < 8; j++)
#pragma unroll
            for (int t = 0; t < 4; t++) acc[i][j][t] = 0.0f;

    for (int k0 = 0; k0 < K; k0 += 16) {
#pragma unroll
        for (int it = 0; it < 2; it++) {
            int i = tid + it * 256;
            int r = i >> 2, kq = (i & 3) * 4;
            float4 v = *(const float4*)&A[(size_t)(row0 + r) * lda + k0 + kq];
            As[kq + 0][r] = f2tf(v.x);
            As[kq + 1][r] = f2tf(v.y);
            As[kq + 2][r] = f2tf(v.z);
            As[kq + 3][r] = f2tf(v.w);
        }
#pragma unroll
        for (int it = 0; it < 2; it++) {
            int i = tid + it * 256;
            int kk = i >> 5, nq = (i & 31) * 4;
            float4 v = *(const float4*)&B[(size_t)(k0 + kk) * ldb + col0 + nq];
            Bs[kk][nq + 0] = f2tf(v.x);
            Bs[kk][nq + 1] = f2tf(v.y);
            Bs[kk][nq + 2] = f2tf(v.z);
            Bs[kk][nq + 3] = f2tf(v.w);
        }
        __syncthreads();

#pragma unroll
        for (int ks = 0; ks < 16; ks += 8) {
            uint32_t a[2][4], b[8][2];
#pragma unroll
            for (int im = 0; im < 2; im++) {
                int m0 = m_base + im * 16;
                a[im][0] = As[ks + lc][m0 + lr];
                a[im][1] = As[ks + lc][m0 + 8 + lr];
                a[im][2] = As[ks + 4 + lc][m0 + lr];
                a[im][3] = As[ks + 4 + lc][m0 + 8 + lr];
            }
#pragma unroll
            for (int in = 0; in < 8; in++) {
                int n0 = n_base + in * 8;
                b[in][0] = Bs[ks + lc][n0 + lr];
                b[in][1] = Bs[ks + 4 + lc][n0 + lr];
            }
#pragma unroll
            for (int im = 0; im < 2; im++)
#pragma unroll
                for (int in = 0; in < 8; in++)
                    mma8(acc[im][in], a[im], b[in]);
        }
        __syncthreads();
    }

#pragma unroll
    for (int im = 0; im < 2; im++) {
#pragma unroll
        for (int in = 0; in < 8; in++) {
            int r0 = row0 + m_base + im * 16 + lr;
            int c0 = col0 + n_base + in * 8 + lc * 2;
            float b0 = bias ? bias[c0] : 0.0f;
            float b1 = bias ? bias[c0 + 1] : 0.0f;
            C[(size_t)r0 * ldc + c0]           = acc[im][in][0] + b0;
            C[(size_t)r0 * ldc + c0 + 1]       = acc[im][in][1] + b1;
            C[(size_t)(r0 + 8) * ldc + c0]     = acc[im][in][2] + b0;
            C[(size_t)(r0 + 8) * ldc + c0 + 1] = acc[im][in][3] + b1;
        }
    }
}

// ---------------------------------------------------------------------------
// Fused attention: scores (+int_matrix,+mask) -> softmax -> attn write -> P@V
// One CTA: 32 query rows x all 1024 keys for one (b,h). 512 threads.
// Dynamic smem layout (bytes):
//   [0,       132096)  Ss[32][1032] fp32 scores/probs
//   [132096,  142336)  Qs[64][40]   tf32 Q tile (k-major)
//   [142336,  211968)  union: Ks[64][260] | Vs[4][64][68] | red[4][2048]
// ---------------------------------------------------------------------------
#define SS_OFF 0
#define QS_OFF 132096
#define KV_OFF 142336
#define FUSED_SMEM 211968

__global__ __launch_bounds__(512) void fused_attn(
    const float* __restrict__ intm, const float* __restrict__ mask,
    float* __restrict__ attn) {

    extern __shared__ char smem[];
    float*    Ss = (float*)(smem + SS_OFF);      // [32][1032]
    uint32_t* Qs = (uint32_t*)(smem + QS_OFF);   // [64][40]
    uint32_t* Ks = (uint32_t*)(smem + KV_OFF);   // [64][260]

    const int tid  = threadIdx.x;
    const int lane = tid & 31;
    const int w    = tid >> 5;          // 0..15
    const int lr   = lane >> 2;
    const int lc   = lane & 3;
    const int bh = blockIdx.y;
    const int b  = bh >> 4;
    const int h  = bh & 15;
    const int n0 = blockIdx.x * 32;

    const float* Q  = g_qkv + (size_t)b * NN_ * QKV_COLS + h * HD_;
    const float* Kp = Q + CC;
    const float* V  = Q + 2 * CC;

    // ---- load Q[32][64] -> Qs (tf32, k-major) : 512 float4, one per thread
    {
        int r = tid >> 4, kq = (tid & 15) * 4;
        float4 v = *(const float4*)&Q[(size_t)(n0 + r) * QKV_COLS + kq];
        Qs[(kq + 0) * 40 + r] = f2tf(v.x);
        Qs[(kq + 1) * 40 + r] = f2tf(v.y);
        Qs[(kq + 2) * 40 + r] = f2tf(v.z);
        Qs[(kq + 3) * 40 + r] = f2tf(v.w);
    }

    // ---- scores: 4 chunks of 256 key columns
    const int wm = w & 1;     // 2 row tiles of 16
    const int wn = w >> 1;    // 8 col tiles of 32
    for (int chunk = 0; chunk < 4; chunk++) {
        int m0 = chunk * 256;
        // load K[m0..m0+256)[64] -> Ks (tf32 k-major): 4096 float4 / 512 thr
#pragma unroll
        for (int it = 0; it < 8; it++) {
            int i = tid + it * 512;
            int r = i >> 4, kq = (i & 15) * 4;
            float4 v = *(const float4*)&Kp[(size_t)(m0 + r) * QKV_COLS + kq];
            Ks[(kq + 0) * 260 + r] = f2tf(v.x);
            Ks[(kq + 1) * 260 + r] = f2tf(v.y);
            Ks[(kq + 2) * 260 + r] = f2tf(v.z);
            Ks[(kq + 3) * 260 + r] = f2tf(v.w);
        }
        __syncthreads();

        float acc[4][4];
#pragma unroll
        for (int j = 0; j < 4; j++)
#pragma unroll
            for (int t = 0; t < 4; t++) acc[j][t] = 0.0f;

#pragma unroll
        for (int ks = 0; ks < 64; ks += 8) {
            uint32_t a[4];
            a[0] = Qs[(ks + lc) * 40 + wm * 16 + lr];
            a[1] = Qs[(ks + lc) * 40 + wm * 16 + 8 + lr];
            a[2] = Qs[(ks + 4 + lc) * 40 + wm * 16 + lr];
            a[3] = Qs[(ks + 4 + lc) * 40 + wm * 16 + 8 + lr];
#pragma unroll
            for (int j = 0; j < 4; j++) {
                uint32_t bf[2];
                bf[0] = Ks[(ks + lc) * 260 + wn * 32 + j * 8 + lr];
                bf[1] = Ks[(ks + 4 + lc) * 260 + wn * 32 + j * 8 + lr];
                mma8(acc[j], a, bf);
            }
        }

        // epilogue: scale, +int_matrix, +mask -> Ss
#pragma unroll
        for (int j = 0; j < 4; j++) {
#pragma unroll
            for (int half = 0; half < 2; half++) {
                int r   = wm * 16 + lr + half * 8;
                int cgl = m0 + wn * 32 + j * 8 + lc * 2;
                size_t aidx = ((size_t)bh * NN_ + n0 + r) * NN_ + cgl;
                size_t midx = ((size_t)b  * NN_ + n0 + r) * NN_ + cgl;
                float2 iv = *(const float2*)&intm[aidx];
                float2 mv = *(const float2*)&mask[midx];
                Ss[r * 1032 + cgl]     = 0.125f * acc[j][half * 2]     + iv.x
                                         + (1.0f - mv.x) * (-1e9f);
                Ss[r * 1032 + cgl + 1] = 0.125f * acc[j][half * 2 + 1] + iv.y
                                         + (1.0f - mv.y) * (-1e9f);
            }
        }
        __syncthreads();
    }

    // ---- softmax: warp w handles rows 2w, 2w+1; write attn to gmem
#pragma unroll
    for (int rr = 0; rr < 2; rr++) {
        int r = w * 2 + rr;
        float* row = &Ss[r * 1032];
        float4 vals[8];
        float mx = -1e30f;
#pragma unroll
        for (int j = 0; j < 8; j++) {
            vals[j] = *(float4*)&row[(lane + j * 32) * 4];
            mx = fmaxf(mx, fmaxf(fmaxf(vals[j].x, vals[j].y), fmaxf(vals[j].z, vals[j].w)));
        }
#pragma unroll
        for (int o = 16; o > 0; o >>= 1) mx = fmaxf(mx, __shfl_xor_sync(0xffffffffu, mx, o));
        float sum = 0.0f;
#pragma unroll
        for (int j = 0; j < 8; j++) {
            vals[j].x = __expf(vals[j].x - mx);
            vals[j].y = __expf(vals[j].y - mx);
            vals[j].z = __expf(vals[j].z - mx);
            vals[j].w = __expf(vals[j].w - mx);
            sum += vals[j].x + vals[j].y + vals[j].z + vals[j].w;
        }
#pragma unroll
        for (int o = 16; o > 0; o >>= 1) sum += __shfl_xor_sync(0xffffffffu, sum, o);
        float inv = 1.0f / sum;
        size_t gbase = ((size_t)bh * NN_ + n0 + r) * NN_;
#pragma unroll
        for (int j = 0; j < 8; j++) {
            float4 e;
            e.x = vals[j].x * inv; e.y = vals[j].y * inv;
            e.z = vals[j].z * inv; e.w = vals[j].w * inv;
            *(float4*)&row[(lane + j * 32) * 4] = e;
            *(float4*)&attn[gbase + (lane + j * 32) * 4] = e;
        }
    }
    __syncthreads();

    // ---- ctx = P @ V, split-K: group g (4 warps) handles k in [g*256,(g+1)*256)
    const int g   = w >> 2;
    const int wg  = w & 3;
    const int cwm = wg & 1;
    const int cwn = wg >> 1;
    const int gtid = tid & 127;
    uint32_t* Vs = (uint32_t*)(smem + KV_OFF + g * 17408);   // [64][68]

    float cacc[4][4];
#pragma unroll
    for (int j = 0; j < 4; j++)
#pragma unroll
        for (int t = 0; t < 4; t++) cacc[j][t] = 0.0f;

    for (int c = 0; c < 4; c++) {
        int kbase = g * 256 + c * 64;
        // load V[kbase..+64)[64] -> Vs : 1024 float4 / 128 thr
#pragma unroll
        for (int it = 0; it < 8; it++) {
            int i = gtid + it * 128;
            int r = i >> 4, dq = (i & 15) * 4;
            float4 v = *(const float4*)&V[(size_t)(kbase + r) * QKV_COLS + dq];
            Vs[r * 68 + dq + 0] = f2tf(v.x);
            Vs[r * 68 + dq + 1] = f2tf(v.y);
            Vs[r * 68 + dq + 2] = f2tf(v.z);
            Vs[r * 68 + dq + 3] = f2tf(v.w);
        }
        __syncthreads();

#pragma unroll
        for (int ks = 0; ks < 64; ks += 8) {
            uint32_t a[4];
            a[0] = f2tf(Ss[(cwm * 16 + lr) * 1032 + kbase + ks + lc]);
            a[1] = f2tf(Ss[(cwm * 16 + 8 + lr) * 1032 + kbase + ks + lc]);
            a[2] = f2tf(Ss[(cwm * 16 + lr) * 1032 + kbase + ks + 4 + lc]);
            a[3] = f2tf(Ss[(cwm * 16 + 8 + lr) * 1032 + kbase + ks + 4 + lc]);
#pragma unroll
            for (int j = 0; j < 4; j++) {
                uint32_t bf[2];
                bf[0] = Vs[(ks + lc) * 68 + cwn * 32 + j * 8 + lr];
                bf[1] = Vs[(ks + 4 + lc) * 68 + cwn * 32 + j * 8 + lr];
                mma8(cacc[j], a, bf);
            }
        }
        __syncthreads();
    }

    // partial sums -> smem (reuse K/V space), reduce across 4 groups
    float* red = (float*)(smem + KV_OFF);   // [4][32][64]
#pragma unroll
    for (int j = 0; j < 4; j++) {
        int d = cwn * 32 + j * 8 + lc * 2;
        red[g * 2048 + (cwm * 16 + lr) * 64 + d]         = cacc[j][0];
        red[g * 2048 + (cwm * 16 + lr) * 64 + d + 1]     = cacc[j][1];
        red[g * 2048 + (cwm * 16 + 8 + lr) * 64 + d]     = cacc[j][2];
        red[g * 2048 + (cwm * 16 + 8 + lr) * 64 + d + 1] = cacc[j][3];
    }
    __syncthreads();
    for (int i = tid; i < 2048; i += 512) {
        int m = i >> 6, d = i & 63;
        float s = red[i] + red[2048 + i] + red[4096 + i] + red[6144 + i];
        g_ctx[((size_t)b * NN_ + n0 + m) * CC + h * HD_ + d] = s;
    }
}

// ---------------------------------------------------------------------------
extern "C" void kernel_launch(void* const* d_in, const int* in_sizes, int n_in,
                              void* d_out, int out_size) {
    const float* x     = (const float*)d_in[0];
    const float* intm  = (const float*)d_in[1];
    const float* mask  = (const float*)d_in[2];
    const float* Wqkv  = (const float*)d_in[3];
    const float* bqkv  = (const float*)d_in[4];
    const float* Wproj = (const float*)d_in[5];
    const float* bproj = (const float*)d_in[6];

    float* out  = (float*)d_out;                        // [4,1024,1024]
    float* attn = out + (size_t)BB * NN_ * CC;          // [4,16,1024,1024]

    float* qkv_ptr = nullptr;
    float* ctx_ptr = nullptr;
    cudaGetSymbolAddress((void**)&qkv_ptr, g_qkv);
    cudaGetSymbolAddress((void**)&ctx_ptr, g_ctx);

    cudaFuncSetAttribute(fused_attn, cudaFuncAttributeMaxDynamicSharedMemorySize,
                         FUSED_SMEM);

    // 1. qkv = x @ W_qkv + b_qkv   (M=4096, N=3072, K=1024)
    gemm_tf32_bias<<<dim3(QKV_COLS / 128, M_ROWS / 128), 256>>>(
        x, Wqkv, bqkv, qkv_ptr, M_ROWS, QKV_COLS, CC, CC, QKV_COLS, QKV_COLS);

    // 2-4. fused scores + softmax + attn write + P@V
    fused_attn<<<dim3(NN_ / 32, BB * HH), 512, FUSED_SMEM>>>(intm, mask, attn);

    // 5. out = ctx @ W_proj + b_proj   (M=4096, N=1024, K=1024)
    gemm_tf32_bias<<<dim3(CC / 128, M_ROWS / 128), 256>>>(
        ctx_ptr, Wproj, bproj, out, M_ROWS, CC, CC, CC, CC, CC);
}

// round 6
// speedup vs baseline: 1.3596x; 1.3596x over previous
#include <cuda_runtime.h>
#include <stdint.h>
#include <math.h>

#define BB 4
#define NN_ 1024
#define CC 1024
#define HH 16
#define HD_ 64
#define M_ROWS (BB * NN_)        // 4096
#define QKV_COLS (3 * CC)        // 3072

__device__ float g_qkv[(size_t)M_ROWS * QKV_COLS];   // 48 MB
__device__ float g_ctx[(size_t)M_ROWS * CC];         // 16 MB

// ---------------------------------------------------------------------------
// helpers
// ---------------------------------------------------------------------------
__device__ __forceinline__ uint32_t f2tf(float f) {
    uint32_t r;
    asm("cvt.rna.tf32.f32 %0, %1;" : "=r"(r) : "f"(f));
    return r;
}

__device__ __forceinline__ void mma8(float* d, const uint32_t* a, const uint32_t* b) {
    asm volatile(
        "mma.sync.aligned.m16n8k8.row.col.f32.tf32.tf32.f32 "
        "{%0,%1,%2,%3}, {%4,%5,%6,%7}, {%8,%9}, {%0,%1,%2,%3};"
        : "+f"(d[0]), "+f"(d[1]), "+f"(d[2]), "+f"(d[3])
        : "r"(a[0]), "r"(a[1]), "r"(a[2]), "r"(a[3]), "r"(b[0]), "r"(b[1]));
}

__device__ __forceinline__ void cp16(void* smem_dst, const void* gmem_src) {
    uint32_t s = (uint32_t)__cvta_generic_to_shared(smem_dst);
    asm volatile("cp.async.cg.shared.global [%0], [%1], 16;\n" :: "r"(s), "l"(gmem_src));
}
#define CP_COMMIT() asm volatile("cp.async.commit_group;\n")
#define CP_WAIT(n)  asm volatile("cp.async.wait_group %0;\n" :: "n"(n))

// ---------------------------------------------------------------------------
// Pipelined NN GEMM + bias, tf32 MMA. C[M,N] = A[M,K] @ B[K,N] + bias[N]
// Block 128x128x16, 256 threads (8 warps, warp tile 32x64), cp.async 2-stage.
// Smem holds RAW fp32; cvt to tf32 at fragment load.
// ---------------------------------------------------------------------------
__global__ __launch_bounds__(256) void gemm_tf32_pipe(
    const float* __restrict__ A, const float* __restrict__ B,
    const float* __restrict__ bias, float* __restrict__ C,
    int K, int lda, int ldb, int ldc) {

    __shared__ float As[2][128][20];   // pad 20: conflict-free a-frag
    __shared__ float Bs[2][16][136];   // pad 136: conflict-free b-frag

    const int tid  = threadIdx.x;
    const int lane = tid & 31;
    const int w    = tid >> 5;
    const int wm   = w & 3;
    const int wn   = w >> 2;
    const int row0 = blockIdx.y * 128;
    const int col0 = blockIdx.x * 128;
    const int m_base = wm * 32;
    const int n_base = wn * 64;
    const int lr = lane >> 2;
    const int lc = lane & 3;

    float acc[2][8][4];
#pragma unroll
    for (int i = 0; i < 2; i++)
#pragma unroll
        for (int j = 0; j < 8; j++)
#pragma unroll
            for (int t = 0; t < 4; t++) acc[i][j][t] = 0.0f;

    const int nk = K / 16;

    // stage loader
    auto load_stage = [&](int t, int s) {
#pragma unroll
        for (int it = 0; it < 2; it++) {
            int i = tid + it * 256;
            int r = i >> 2, seg = (i & 3) * 4;
            cp16(&As[s][r][seg], &A[(size_t)(row0 + r) * lda + t * 16 + seg]);
        }
#pragma unroll
        for (int it = 0; it < 2; it++) {
            int i = tid + it * 256;
            int kk = i >> 5, nq = (i & 31) * 4;
            cp16(&Bs[s][kk][nq], &B[(size_t)(t * 16 + kk) * ldb + col0 + nq]);
        }
    };

    load_stage(0, 0);
    CP_COMMIT();

    for (int t = 0; t < nk; t++) {
        if (t + 1 < nk) {
            load_stage(t + 1, (t + 1) & 1);
            CP_COMMIT();
            CP_WAIT(1);
        } else {
            CP_WAIT(0);
        }
        __syncthreads();
        const int s = t & 1;

#pragma unroll
        for (int ks = 0; ks < 16; ks += 8) {
            uint32_t a[2][4], b[8][2];
#pragma unroll
            for (int im = 0; im < 2; im++) {
                int m0 = m_base + im * 16;
                a[im][0] = f2tf(As[s][m0 + lr][ks + lc]);
                a[im][1] = f2tf(As[s][m0 + 8 + lr][ks + lc]);
                a[im][2] = f2tf(As[s][m0 + lr][ks + 4 + lc]);
                a[im][3] = f2tf(As[s][m0 + 8 + lr][ks + 4 + lc]);
            }
#pragma unroll
            for (int in = 0; in < 8; in++) {
                int n0 = n_base + in * 8;
                b[in][0] = f2tf(Bs[s][ks + lc][n0 + lr]);
                b[in][1] = f2tf(Bs[s][ks + 4 + lc][n0 + lr]);
            }
#pragma unroll
            for (int im = 0; im < 2; im++)
#pragma unroll
                for (int in = 0; in < 8; in++)
                    mma8(acc[im][in], a[im], b[in]);
        }
        __syncthreads();
    }

#pragma unroll
    for (int im = 0; im < 2; im++) {
#pragma unroll
        for (int in = 0; in < 8; in++) {
            int r0 = row0 + m_base + im * 16 + lr;
            int c0 = col0 + n_base + in * 8 + lc * 2;
            float b0 = bias[c0];
            float b1 = bias[c0 + 1];
            C[(size_t)r0 * ldc + c0]           = acc[im][in][0] + b0;
            C[(size_t)r0 * ldc + c0 + 1]       = acc[im][in][1] + b1;
            C[(size_t)(r0 + 8) * ldc + c0]     = acc[im][in][2] + b0;
            C[(size_t)(r0 + 8) * ldc + c0 + 1] = acc[im][in][3] + b1;
        }
    }
}

// ---------------------------------------------------------------------------
// Fused scores + softmax. CTA = 32 query rows x all 1024 keys for one (b,h).
// 512 threads = 16 warps: wm = w&1 (16-row block), wn = w>>1 (16-key block
// within a 128-key chunk). Scores live in registers (s[8][2][4] per lane).
// K streamed through cp.async double buffer. Single attn write.
// Dynamic smem (floats): Qs[32][68] | Ks[2][128][68] | red[32][8] | rowv[32]
// ---------------------------------------------------------------------------
#define SSM_QS   0
#define SSM_KS   2176
#define SSM_KSZ  8704
#define SSM_RED  (SSM_KS + 2 * SSM_KSZ)       // 19584
#define SSM_ROWV (SSM_RED + 256)              // 19840
#define SSM_TOTF (SSM_ROWV + 32)              // 19872 floats = 79488 B

__global__ __launch_bounds__(512) void scores_softmax(
    const float* __restrict__ intm, const float* __restrict__ mask,
    float* __restrict__ attn) {

    extern __shared__ float sm[];
    float* Qs   = sm + SSM_QS;
    float* red  = sm + SSM_RED;
    float* rowv = sm + SSM_ROWV;

    const int tid  = threadIdx.x;
    const int lane = tid & 31;
    const int w    = tid >> 5;          // 0..15
    const int lr   = lane >> 2;
    const int lc   = lane & 3;
    const int wm   = w & 1;
    const int wn   = w >> 1;
    const int bh = blockIdx.y;
    const int b  = bh >> 4;
    const int h  = bh & 15;
    const int n0 = blockIdx.x * 32;

    const float* Q  = g_qkv + (size_t)b * NN_ * QKV_COLS + h * HD_;
    const float* Kp = Q + CC;

    // load Q[32][64] raw -> Qs
    {
        int r = tid >> 4, q = (tid & 15) * 4;
        float4 v = *(const float4*)&Q[(size_t)(n0 + r) * QKV_COLS + q];
        Qs[r * 68 + q + 0] = v.x;
        Qs[r * 68 + q + 1] = v.y;
        Qs[r * 68 + q + 2] = v.z;
        Qs[r * 68 + q + 3] = v.w;
    }

    auto load_chunk = [&](int c, int s) {
        float* Kb = sm + SSM_KS + s * SSM_KSZ;
#pragma unroll
        for (int t = 0; t < 4; t++) {
            int i = tid + t * 512;
            int key = i >> 4, seg = (i & 15) * 4;
            cp16(&Kb[key * 68 + seg], &Kp[(size_t)(c * 128 + key) * QKV_COLS + seg]);
        }
    };

    float sreg[8][2][4];
#pragma unroll
    for (int c = 0; c < 8; c++)
#pragma unroll
        for (int in = 0; in < 2; in++)
#pragma unroll
            for (int t = 0; t < 4; t++) sreg[c][in][t] = 0.0f;

    load_chunk(0, 0);
    CP_COMMIT();

    const int qbase = wm * 16;
    for (int c = 0; c < 8; c++) {
        if (c + 1 < 8) {
            load_chunk(c + 1, (c + 1) & 1);
            CP_COMMIT();
            CP_WAIT(1);
        } else {
            CP_WAIT(0);
        }
        __syncthreads();
        float* Kb = sm + SSM_KS + (c & 1) * SSM_KSZ;

#pragma unroll
        for (int ks = 0; ks < 64; ks += 8) {
            uint32_t a[4];
            a[0] = f2tf(Qs[(qbase + lr) * 68 + ks + lc]);
            a[1] = f2tf(Qs[(qbase + 8 + lr) * 68 + ks + lc]);
            a[2] = f2tf(Qs[(qbase + lr) * 68 + ks + 4 + lc]);
            a[3] = f2tf(Qs[(qbase + 8 + lr) * 68 + ks + 4 + lc]);
#pragma unroll
            for (int in = 0; in < 2; in++) {
                uint32_t bf[2];
                int key = wn * 16 + in * 8 + lr;
                bf[0] = f2tf(Kb[key * 68 + ks + lc]);
                bf[1] = f2tf(Kb[key * 68 + ks + 4 + lc]);
                mma8(sreg[c][in], a, bf);
            }
        }

        // epilogue: scale + int_matrix + mask (reads overlap next chunk's cp.async)
#pragma unroll
        for (int in = 0; in < 2; in++) {
#pragma unroll
            for (int hh = 0; hh < 2; hh++) {
                int r   = qbase + lr + hh * 8;
                int key = c * 128 + wn * 16 + in * 8 + lc * 2;
                size_t aidx = ((size_t)bh * NN_ + n0 + r) * NN_ + key;
                size_t midx = ((size_t)b  * NN_ + n0 + r) * NN_ + key;
                float2 iv = *(const float2*)&intm[aidx];
                float2 mv = *(const float2*)&mask[midx];
                sreg[c][in][hh * 2]     = 0.125f * sreg[c][in][hh * 2]     + iv.x
                                          + (1.0f - mv.x) * (-1e9f);
                sreg[c][in][hh * 2 + 1] = 0.125f * sreg[c][in][hh * 2 + 1] + iv.y
                                          + (1.0f - mv.y) * (-1e9f);
            }
        }
        __syncthreads();
    }

    // ---- softmax over registers (rows qbase+lr, qbase+8+lr)
    float mx[2] = {-1e30f, -1e30f};
#pragma unroll
    for (int c = 0; c < 8; c++)
#pragma unroll
        for (int in = 0; in < 2; in++)
#pragma unroll
            for (int hh = 0; hh < 2; hh++)
                mx[hh] = fmaxf(mx[hh],
                               fmaxf(sreg[c][in][hh * 2], sreg[c][in][hh * 2 + 1]));
#pragma unroll
    for (int hh = 0; hh < 2; hh++) {
        mx[hh] = fmaxf(mx[hh], __shfl_xor_sync(0xffffffffu, mx[hh], 1));
        mx[hh] = fmaxf(mx[hh], __shfl_xor_sync(0xffffffffu, mx[hh], 2));
    }
    if (lc == 0) {
        red[(qbase + lr) * 8 + wn]     = mx[0];
        red[(qbase + 8 + lr) * 8 + wn] = mx[1];
    }
    __syncthreads();
    if (tid < 32) {
        float m = red[tid * 8];
#pragma unroll
        for (int j = 1; j < 8; j++) m = fmaxf(m, red[tid * 8 + j]);
        rowv[tid] = m;
    }
    __syncthreads();
    float rmx[2] = {rowv[qbase + lr], rowv[qbase + 8 + lr]};
    __syncthreads();

    float sum[2] = {0.0f, 0.0f};
#pragma unroll
    for (int c = 0; c < 8; c++)
#pragma unroll
        for (int in = 0; in < 2; in++)
#pragma unroll
            for (int hh = 0; hh < 2; hh++) {
                float e0 = __expf(sreg[c][in][hh * 2]     - rmx[hh]);
                float e1 = __expf(sreg[c][in][hh * 2 + 1] - rmx[hh]);
                sreg[c][in][hh * 2]     = e0;
                sreg[c][in][hh * 2 + 1] = e1;
                sum[hh] += e0 + e1;
            }
#pragma unroll
    for (int hh = 0; hh < 2; hh++) {
        sum[hh] += __shfl_xor_sync(0xffffffffu, sum[hh], 1);
        sum[hh] += __shfl_xor_sync(0xffffffffu, sum[hh], 2);
    }
    if (lc == 0) {
        red[(qbase + lr) * 8 + wn]     = sum[0];
        red[(qbase + 8 + lr) * 8 + wn] = sum[1];
    }
    __syncthreads();
    if (tid < 32) {
        float s = 0.0f;
#pragma unroll
        for (int j = 0; j < 8; j++) s += red[tid * 8 + j];
        rowv[tid] = 1.0f / s;
    }
    __syncthreads();
    float inv[2] = {rowv[qbase + lr], rowv[qbase + 8 + lr]};

    // ---- write attn
#pragma unroll
    for (int c = 0; c < 8; c++)
#pragma unroll
        for (int in = 0; in < 2; in++)
#pragma unroll
            for (int hh = 0; hh < 2; hh++) {
                int r   = qbase + lr + hh * 8;
                int key = c * 128 + wn * 16 + in * 8 + lc * 2;
                size_t aidx = ((size_t)bh * NN_ + n0 + r) * NN_ + key;
                float2 e;
                e.x = sreg[c][in][hh * 2] * inv[hh];
                e.y = sreg[c][in][hh * 2 + 1] * inv[hh];
                *(float2*)&attn[aidx] = e;
            }
}

// ---------------------------------------------------------------------------
// ctx = attn @ V per (b,h). Block 128x64x16, 256 thr (8 warps, 16x64 each),
// cp.async 2-stage. Output [b, n, h, hd] into g_ctx.
// ---------------------------------------------------------------------------
__global__ __launch_bounds__(256) void ctx_tf32_pipe(const float* __restrict__ attn) {
    __shared__ float As[2][128][20];
    __shared__ float Vs[2][16][72];

    const int tid  = threadIdx.x;
    const int lane = tid & 31;
    const int w    = tid >> 5;
    const int bh = blockIdx.z;
    const int b  = bh >> 4;
    const int h  = bh & 15;
    const float* A = attn + (size_t)bh * NN_ * NN_;
    const float* V = g_qkv + (size_t)b * NN_ * QKV_COLS + 2 * CC + h * HD_;

    const int row0 = blockIdx.y * 128;
    const int m_base = w * 16;
    const int lr = lane >> 2;
    const int lc = lane & 3;

    float acc[8][4];
#pragma unroll
    for (int j = 0; j < 8; j++)
#pragma unroll
        for (int t = 0; t < 4; t++) acc[j][t] = 0.0f;

    auto load_stage = [&](int t, int s) {
#pragma unroll
        for (int it = 0; it < 2; it++) {
            int i = tid + it * 256;
            int r = i >> 2, seg = (i & 3) * 4;
            cp16(&As[s][r][seg], &A[(size_t)(row0 + r) * NN_ + t * 16 + seg]);
        }
        {
            int kk = tid >> 4, dq = (tid & 15) * 4;
            cp16(&Vs[s][kk][dq], &V[(size_t)(t * 16 + kk) * QKV_COLS + dq]);
        }
    };

    load_stage(0, 0);
    CP_COMMIT();

    for (int t = 0; t < 64; t++) {
        if (t + 1 < 64) {
            load_stage(t + 1, (t + 1) & 1);
            CP_COMMIT();
            CP_WAIT(1);
        } else {
            CP_WAIT(0);
        }
        __syncthreads();
        const int s = t & 1;

#pragma unroll
        for (int ks = 0; ks < 16; ks += 8) {
            uint32_t a[4], bf[8][2];
            a[0] = f2tf(As[s][m_base + lr][ks + lc]);
            a[1] = f2tf(As[s][m_base + 8 + lr][ks + lc]);
            a[2] = f2tf(As[s][m_base + lr][ks + 4 + lc]);
            a[3] = f2tf(As[s][m_base + 8 + lr][ks + 4 + lc]);
#pragma unroll
            for (int in = 0; in < 8; in++) {
                bf[in][0] = f2tf(Vs[s][ks + lc][in * 8 + lr]);
                bf[in][1] = f2tf(Vs[s][ks + 4 + lc][in * 8 + lr]);
            }
#pragma unroll
            for (int in = 0; in < 8; in++)
                mma8(acc[in], a, bf[in]);
        }
        __syncthreads();
    }

#pragma unroll
    for (int in = 0; in < 8; in++) {
#pragma unroll
        for (int half = 0; half < 2; half++) {
            int n = row0 + m_base + lr + half * 8;
            int d = in * 8 + lc * 2;
            size_t idx = ((size_t)b * NN_ + n) * CC + h * HD_ + d;
            g_ctx[idx]     = acc[in][half * 2];
            g_ctx[idx + 1] = acc[in][half * 2 + 1];
        }
    }
}

// ---------------------------------------------------------------------------
extern "C" void kernel_launch(void* const* d_in, const int* in_sizes, int n_in,
                              void* d_out, int out_size) {
    const float* x     = (const float*)d_in[0];
    const float* intm  = (const float*)d_in[1];
    const float* mask  = (const float*)d_in[2];
    const float* Wqkv  = (const float*)d_in[3];
    const float* bqkv  = (const float*)d_in[4];
    const float* Wproj = (const float*)d_in[5];
    const float* bproj = (const float*)d_in[6];

    float* out  = (float*)d_out;                        // [4,1024,1024]
    float* attn = out + (size_t)BB * NN_ * CC;          // [4,16,1024,1024]

    float* qkv_ptr = nullptr;
    float* ctx_ptr = nullptr;
    cudaGetSymbolAddress((void**)&qkv_ptr, g_qkv);
    cudaGetSymbolAddress((void**)&ctx_ptr, g_ctx);

    static bool attr_set = false;
    if (!attr_set) {
        cudaFuncSetAttribute(scores_softmax,
                             cudaFuncAttributeMaxDynamicSharedMemorySize,
                             SSM_TOTF * 4);
        attr_set = true;
    }

    // 1. qkv = x @ W_qkv + b_qkv   (M=4096, N=3072, K=1024)
    gemm_tf32_pipe<<<dim3(QKV_COLS / 128, M_ROWS / 128), 256>>>(
        x, Wqkv, bqkv, qkv_ptr, CC, CC, QKV_COLS, QKV_COLS);

    // 2-3. fused scores (+int_matrix,+mask) + softmax -> attn
    scores_softmax<<<dim3(NN_ / 32, BB * HH), 512, SSM_TOTF * 4>>>(intm, mask, attn);

    // 4. ctx = attn @ V
    ctx_tf32_pipe<<<dim3(1, NN_ / 128, BB * HH), 256>>>(attn);

    // 5. out = ctx @ W_proj + b_proj   (M=4096, N=1024, K=1024)
    gemm_tf32_pipe<<<dim3(CC / 128, M_ROWS / 128), 256>>>(
        ctx_ptr, Wproj, bproj, out, CC, CC, CC, CC);
}

// round 7
// speedup vs baseline: 2.1871x; 1.6086x over previous
#include <cuda_runtime.h>
#include <cuda_fp16.h>
#include <stdint.h>
#include <math.h>

#define BB 4
#define NN_ 1024
#define CC 1024
#define HH 16
#define HD_ 64
#define M_ROWS (BB * NN_)        // 4096
#define QKV_COLS (3 * CC)        // 3072

// fp16 scratch (device globals: allocation-free)
__device__ __half g_xh[(size_t)M_ROWS * CC];            //  8 MB
__device__ __half g_wqkvh[(size_t)CC * QKV_COLS];       //  6 MB
__device__ __half g_wprojh[(size_t)CC * CC];            //  2 MB
__device__ __half g_qkvh[(size_t)M_ROWS * QKV_COLS];    // 24 MB
__device__ __half g_p[(size_t)BB * HH * NN_ * NN_];     // 128 MB
__device__ __half g_ctxh[(size_t)M_ROWS * CC];          //  8 MB

// ---------------------------------------------------------------------------
// helpers
// ---------------------------------------------------------------------------
__device__ __forceinline__ void mma16(float* d, const uint32_t* a,
                                      uint32_t b0, uint32_t b1) {
    asm volatile(
        "mma.sync.aligned.m16n8k16.row.col.f32.f16.f16.f32 "
        "{%0,%1,%2,%3}, {%4,%5,%6,%7}, {%8,%9}, {%0,%1,%2,%3};"
        : "+f"(d[0]), "+f"(d[1]), "+f"(d[2]), "+f"(d[3])
        : "r"(a[0]), "r"(a[1]), "r"(a[2]), "r"(a[3]), "r"(b0), "r"(b1));
}

__device__ __forceinline__ void ldmx4(uint32_t* r, const void* p) {
    uint32_t s = (uint32_t)__cvta_generic_to_shared(p);
    asm volatile("ldmatrix.sync.aligned.m8n8.x4.shared.b16 {%0,%1,%2,%3}, [%4];"
                 : "=r"(r[0]), "=r"(r[1]), "=r"(r[2]), "=r"(r[3]) : "r"(s));
}

__device__ __forceinline__ void ldmx4t(uint32_t* r, const void* p) {
    uint32_t s = (uint32_t)__cvta_generic_to_shared(p);
    asm volatile("ldmatrix.sync.aligned.m8n8.x4.trans.shared.b16 {%0,%1,%2,%3}, [%4];"
                 : "=r"(r[0]), "=r"(r[1]), "=r"(r[2]), "=r"(r[3]) : "r"(s));
}

__device__ __forceinline__ void cp16(void* smem_dst, const void* gmem_src) {
    uint32_t s = (uint32_t)__cvta_generic_to_shared(smem_dst);
    asm volatile("cp.async.cg.shared.global [%0], [%1], 16;\n" :: "r"(s), "l"(gmem_src));
}
#define CP_COMMIT() asm volatile("cp.async.commit_group;\n")
#define CP_WAIT(n)  asm volatile("cp.async.wait_group %0;\n" :: "n"(n))

// ---------------------------------------------------------------------------
// fp32 -> fp16 elementwise convert
// ---------------------------------------------------------------------------
__global__ void f2h_kernel(const float4* __restrict__ in, __half2* __restrict__ out,
                           int n4) {
    int i = blockIdx.x * blockDim.x + threadIdx.x;
    if (i < n4) {
        float4 v = in[i];
        out[2 * i]     = __floats2half2_rn(v.x, v.y);
        out[2 * i + 1] = __floats2half2_rn(v.z, v.w);
    }
}

// ---------------------------------------------------------------------------
// fp16 GEMM: C[M,N] = A[M,K] @ B[K,N] (+ bias). Block 128xBN, BK=32,
// 256 threads, 2-stage cp.async, ldmatrix fragments, fp32 accum.
// OUTH: write __half C, else float C.
// ---------------------------------------------------------------------------
template <int BN, bool OUTH>
__global__ __launch_bounds__(256) void gemm_h(
    const __half* __restrict__ A, const __half* __restrict__ B,
    const float* __restrict__ bias, void* __restrict__ Cv,
    int K, int lda, int ldb, int ldc) {

    constexpr int NW_N = BN / 64;          // 2 (BN=128) or 1 (BN=64)
    constexpr int NW_M = 8 / NW_N;         // 4 or 8
    constexpr int WTM  = 128 / NW_M;       // 32 or 16
    constexpr int MT   = WTM / 16;         // 2 or 1
    constexpr int BPAD = BN + 8;

    __shared__ __half As[2][128][40];      // [m][k] pitch 40 (80B: (5m)%8 distinct)
    __shared__ __half Bs[2][32][BPAD];     // [k][n] pitch BN+8

    const int tid  = threadIdx.x;
    const int lane = tid & 31;
    const int w    = tid >> 5;
    const int wm   = w % NW_M;
    const int wn   = w / NW_M;
    const int row0 = blockIdx.y * 128;
    const int col0 = blockIdx.x * BN;
    const int m_base = wm * WTM;
    const int n_base = wn * 64;
    const int lr = lane >> 2;
    const int lc = lane & 3;
    const int l15  = lane & 15;
    const int lhi8 = (lane >> 4) << 3;

    float acc[MT][8][4];
#pragma unroll
    for (int i = 0; i < MT; i++)
#pragma unroll
        for (int j = 0; j < 8; j++)
#pragma unroll
            for (int t = 0; t < 4; t++) acc[i][j][t] = 0.0f;

    auto load_stage = [&](int t, int s) {
#pragma unroll
        for (int it = 0; it < 2; it++) {                 // A: 128x32 halves
            int i = tid + it * 256;
            int r = i >> 2, seg = (i & 3) * 8;
            cp16(&As[s][r][seg], &A[(size_t)(row0 + r) * lda + t * 32 + seg]);
        }
#pragma unroll
        for (int it = 0; it < BN / 64; it++) {           // B: 32xBN halves
            int i = tid + it * 256;
            int kk = i / (BN / 8), nq = (i % (BN / 8)) * 8;
            cp16(&Bs[s][kk][nq], &B[(size_t)(t * 32 + kk) * ldb + col0 + nq]);
        }
    };

    load_stage(0, 0);
    CP_COMMIT();

    const int nk = K / 32;
    for (int t = 0; t < nk; t++) {
        if (t + 1 < nk) {
            load_stage(t + 1, (t + 1) & 1);
            CP_COMMIT();
            CP_WAIT(1);
        } else {
            CP_WAIT(0);
        }
        __syncthreads();
        const int s = t & 1;

#pragma unroll
        for (int kst = 0; kst < 32; kst += 16) {
            uint32_t a[MT][4], bfr[4][4];
#pragma unroll
            for (int mt = 0; mt < MT; mt++)
                ldmx4(a[mt], &As[s][m_base + mt * 16 + l15][kst + lhi8]);
#pragma unroll
            for (int nt = 0; nt < 4; nt++)
                ldmx4t(bfr[nt], &Bs[s][kst + l15][n_base + nt * 16 + lhi8]);
#pragma unroll
            for (int mt = 0; mt < MT; mt++)
#pragma unroll
                for (int nt = 0; nt < 4; nt++) {
                    mma16(acc[mt][2 * nt],     a[mt], bfr[nt][0], bfr[nt][1]);
                    mma16(acc[mt][2 * nt + 1], a[mt], bfr[nt][2], bfr[nt][3]);
                }
        }
        __syncthreads();
    }

    // epilogue
#pragma unroll
    for (int mt = 0; mt < MT; mt++) {
#pragma unroll
        for (int in = 0; in < 8; in++) {
            int r0 = row0 + m_base + mt * 16 + lr;
            int c0 = col0 + n_base + in * 8 + lc * 2;
            float b0 = bias ? bias[c0] : 0.0f;
            float b1 = bias ? bias[c0 + 1] : 0.0f;
            if (OUTH) {
                __half* C = (__half*)Cv;
                *(__half2*)&C[(size_t)r0 * ldc + c0] =
                    __floats2half2_rn(acc[mt][in][0] + b0, acc[mt][in][1] + b1);
                *(__half2*)&C[(size_t)(r0 + 8) * ldc + c0] =
                    __floats2half2_rn(acc[mt][in][2] + b0, acc[mt][in][3] + b1);
            } else {
                float* C = (float*)Cv;
                C[(size_t)r0 * ldc + c0]           = acc[mt][in][0] + b0;
                C[(size_t)r0 * ldc + c0 + 1]       = acc[mt][in][1] + b1;
                C[(size_t)(r0 + 8) * ldc + c0]     = acc[mt][in][2] + b0;
                C[(size_t)(r0 + 8) * ldc + c0 + 1] = acc[mt][in][3] + b1;
            }
        }
    }
}

// ---------------------------------------------------------------------------
// ctx = P @ V per (b,h). Block 128x64, BK=32, 256 thr (8 warps, 16x64 each).
// P fp16 [bh][n][key], V fp16 inside g_qkvh. Output fp16 g_ctxh [b,n,h*64+d].
// ---------------------------------------------------------------------------
__global__ __launch_bounds__(256) void ctx_h(const __half* __restrict__ P) {
    __shared__ __half As[2][128][40];
    __shared__ __half Bs[2][32][72];

    const int tid  = threadIdx.x;
    const int lane = tid & 31;
    const int w    = tid >> 5;
    const int bh = blockIdx.z;
    const int b  = bh >> 4;
    const int h  = bh & 15;
    const __half* A = P + (size_t)bh * NN_ * NN_;
    const __half* V = g_qkvh + (size_t)b * NN_ * QKV_COLS + 2 * CC + h * HD_;
    __half* Ch = g_ctxh + (size_t)b * NN_ * CC + h * HD_;

    const int row0 = blockIdx.y * 128;
    const int m_base = w * 16;
    const int lr = lane >> 2;
    const int lc = lane & 3;
    const int l15  = lane & 15;
    const int lhi8 = (lane >> 4) << 3;

    float acc[8][4];
#pragma unroll
    for (int j = 0; j < 8; j++)
#pragma unroll
        for (int t = 0; t < 4; t++) acc[j][t] = 0.0f;

    auto load_stage = [&](int t, int s) {
#pragma unroll
        for (int it = 0; it < 2; it++) {                 // P: 128x32 halves
            int i = tid + it * 256;
            int r = i >> 2, seg = (i & 3) * 8;
            cp16(&As[s][r][seg], &A[(size_t)(row0 + r) * NN_ + t * 32 + seg]);
        }
        {                                                // V: 32x64 halves
            int kk = tid >> 3, nq = (tid & 7) * 8;
            cp16(&Bs[s][kk][nq], &V[(size_t)(t * 32 + kk) * QKV_COLS + nq]);
        }
    };

    load_stage(0, 0);
    CP_COMMIT();

    for (int t = 0; t < 32; t++) {
        if (t + 1 < 32) {
            load_stage(t + 1, (t + 1) & 1);
            CP_COMMIT();
            CP_WAIT(1);
        } else {
            CP_WAIT(0);
        }
        __syncthreads();
        const int s = t & 1;

#pragma unroll
        for (int kst = 0; kst < 32; kst += 16) {
            uint32_t a[4], bfr[4][4];
            ldmx4(a, &As[s][m_base + l15][kst + lhi8]);
#pragma unroll
            for (int nt = 0; nt < 4; nt++)
                ldmx4t(bfr[nt], &Bs[s][kst + l15][nt * 16 + lhi8]);
#pragma unroll
            for (int nt = 0; nt < 4; nt++) {
                mma16(acc[2 * nt],     a, bfr[nt][0], bfr[nt][1]);
                mma16(acc[2 * nt + 1], a, bfr[nt][2], bfr[nt][3]);
            }
        }
        __syncthreads();
    }

#pragma unroll
    for (int in = 0; in < 8; in++) {
        int r0 = row0 + m_base + lr;
        int c0 = in * 8 + lc * 2;
        *(__half2*)&Ch[(size_t)r0 * CC + c0] =
            __floats2half2_rn(acc[in][0], acc[in][1]);
        *(__half2*)&Ch[(size_t)(r0 + 8) * CC + c0] =
            __floats2half2_rn(acc[in][2], acc[in][3]);
    }
}

// ---------------------------------------------------------------------------
// Fused scores + softmax (fp16 MMA). CTA = 32 rows x 1024 keys, one (b,h).
// 512 threads = 16 warps (wm = w&1 row-block of 16, wn = w>>1 key-block of 16).
// Q frags hoisted to regs; K streamed 128-key chunks via cp.async.
// Writes attn fp32 (output) and P fp16 (for ctx GEMM).
// ---------------------------------------------------------------------------
__global__ __launch_bounds__(512) void scores_softmax_h(
    const float* __restrict__ intm, const float* __restrict__ mask,
    float* __restrict__ attn) {

    __shared__ __half Qs[32][72];
    __shared__ __half Ks[2][128][72];
    __shared__ float red[32][8];
    __shared__ float rowv[32];

    const int tid  = threadIdx.x;
    const int lane = tid & 31;
    const int w    = tid >> 5;
    const int lr   = lane >> 2;
    const int lc   = lane & 3;
    const int wm   = w & 1;
    const int wn   = w >> 1;
    const int l15  = lane & 15;
    const int lhi8 = (lane >> 4) << 3;
    const int bh = blockIdx.y;
    const int b  = bh >> 4;
    const int h  = bh & 15;
    const int n0 = blockIdx.x * 32;

    const __half* Q  = g_qkvh + (size_t)b * NN_ * QKV_COLS + h * HD_;
    const __half* Kp = Q + CC;

    // load Q[32][64] halves (256 x 16B)
    if (tid < 256) {
        int r = tid >> 3, seg = (tid & 7) * 8;
        *(uint4*)&Qs[r][seg] = *(const uint4*)&Q[(size_t)(n0 + r) * QKV_COLS + seg];
    }

    auto load_chunk = [&](int c, int s) {
#pragma unroll
        for (int it = 0; it < 2; it++) {                 // 128 keys x 64 halves
            int i = tid + it * 512;
            int key = i >> 3, seg = (i & 7) * 8;
            cp16(&Ks[s][key][seg], &Kp[(size_t)(c * 128 + key) * QKV_COLS + seg]);
        }
    };

    load_chunk(0, 0);
    CP_COMMIT();
    __syncthreads();

    // hoist Q fragments (4 k16 steps)
    const int qbase = wm * 16;
    uint32_t aQ[4][4];
#pragma unroll
    for (int ks = 0; ks < 4; ks++)
        ldmx4(aQ[ks], &Qs[qbase + l15][ks * 16 + lhi8]);

    float sreg[8][2][4];
#pragma unroll
    for (int c = 0; c < 8; c++)
#pragma unroll
        for (int in = 0; in < 2; in++)
#pragma unroll
            for (int t = 0; t < 4; t++) sreg[c][in][t] = 0.0f;

    for (int c = 0; c < 8; c++) {
        if (c + 1 < 8) {
            load_chunk(c + 1, (c + 1) & 1);
            CP_COMMIT();
            CP_WAIT(1);
        } else {
            CP_WAIT(0);
        }
        __syncthreads();
        const int s = c & 1;

#pragma unroll
        for (int ks = 0; ks < 4; ks++) {
            uint32_t bfr[4];
            // non-trans ldmatrix on [key][hd]: r0=(n0-7,k0-7), r1=(n8-15,k0-7),
            // r2=(n0-7,k8-15), r3=(n8-15,k8-15) -> pairs {r0,r2}, {r1,r3}
            ldmx4(bfr, &Ks[s][wn * 16 + l15][ks * 16 + lhi8]);
            mma16(sreg[c][0], aQ[ks], bfr[0], bfr[2]);
            mma16(sreg[c][1], aQ[ks], bfr[1], bfr[3]);
        }

        // epilogue: scale + int_matrix + mask
#pragma unroll
        for (int in = 0; in < 2; in++) {
#pragma unroll
            for (int hh = 0; hh < 2; hh++) {
                int r   = qbase + lr + hh * 8;
                int key = c * 128 + wn * 16 + in * 8 + lc * 2;
                size_t aidx = ((size_t)bh * NN_ + n0 + r) * NN_ + key;
                size_t midx = ((size_t)b  * NN_ + n0 + r) * NN_ + key;
                float2 iv = *(const float2*)&intm[aidx];
                float2 mv = *(const float2*)&mask[midx];
                sreg[c][in][hh * 2]     = 0.125f * sreg[c][in][hh * 2]     + iv.x
                                          + (1.0f - mv.x) * (-1e9f);
                sreg[c][in][hh * 2 + 1] = 0.125f * sreg[c][in][hh * 2 + 1] + iv.y
                                          + (1.0f - mv.y) * (-1e9f);
            }
        }
        __syncthreads();
    }

    // ---- softmax over registers (rows qbase+lr, qbase+8+lr)
    float mx[2] = {-1e30f, -1e30f};
#pragma unroll
    for (int c = 0; c < 8; c++)
#pragma unroll
        for (int in = 0; in < 2; in++)
#pragma unroll
            for (int hh = 0; hh < 2; hh++)
                mx[hh] = fmaxf(mx[hh],
                               fmaxf(sreg[c][in][hh * 2], sreg[c][in][hh * 2 + 1]));
#pragma unroll
    for (int hh = 0; hh < 2; hh++) {
        mx[hh] = fmaxf(mx[hh], __shfl_xor_sync(0xffffffffu, mx[hh], 1));
        mx[hh] = fmaxf(mx[hh], __shfl_xor_sync(0xffffffffu, mx[hh], 2));
    }
    if (lc == 0) {
        red[qbase + lr][wn]     = mx[0];
        red[qbase + 8 + lr][wn] = mx[1];
    }
    __syncthreads();
    if (tid < 32) {
        float m = red[tid][0];
#pragma unroll
        for (int j = 1; j < 8; j++) m = fmaxf(m, red[tid][j]);
        rowv[tid] = m;
    }
    __syncthreads();
    float rmx[2] = {rowv[qbase + lr], rowv[qbase + 8 + lr]};
    __syncthreads();

    float sum[2] = {0.0f, 0.0f};
#pragma unroll
    for (int c = 0; c < 8; c++)
#pragma unroll
        for (int in = 0; in < 2; in++)
#pragma unroll
            for (int hh = 0; hh < 2; hh++) {
                float e0 = __expf(sreg[c][in][hh * 2]     - rmx[hh]);
                float e1 = __expf(sreg[c][in][hh * 2 + 1] - rmx[hh]);
                sreg[c][in][hh * 2]     = e0;
                sreg[c][in][hh * 2 + 1] = e1;
                sum[hh] += e0 + e1;
            }
#pragma unroll
    for (int hh = 0; hh < 2; hh++) {
        sum[hh] += __shfl_xor_sync(0xffffffffu, sum[hh], 1);
        sum[hh] += __shfl_xor_sync(0xffffffffu, sum[hh], 2);
    }
    if (lc == 0) {
        red[qbase + lr][wn]     = sum[0];
        red[qbase + 8 + lr][wn] = sum[1];
    }
    __syncthreads();
    if (tid < 32) {
        float s = 0.0f;
#pragma unroll
        for (int j = 0; j < 8; j++) s += red[tid][j];
        rowv[tid] = 1.0f / s;
    }
    __syncthreads();
    float inv[2] = {rowv[qbase + lr], rowv[qbase + 8 + lr]};

    // ---- write attn (fp32, required output) and P (fp16, for ctx)
#pragma unroll
    for (int c = 0; c < 8; c++)
#pragma unroll
        for (int in = 0; in < 2; in++)
#pragma unroll
            for (int hh = 0; hh < 2; hh++) {
                int r   = qbase + lr + hh * 8;
                int key = c * 128 + wn * 16 + in * 8 + lc * 2;
                size_t aidx = ((size_t)bh * NN_ + n0 + r) * NN_ + key;
                float2 e;
                e.x = sreg[c][in][hh * 2] * inv[hh];
                e.y = sreg[c][in][hh * 2 + 1] * inv[hh];
                *(float2*)&attn[aidx] = e;
                *(__half2*)&g_p[aidx] = __floats2half2_rn(e.x, e.y);
            }
}

// ---------------------------------------------------------------------------
extern "C" void kernel_launch(void* const* d_in, const int* in_sizes, int n_in,
                              void* d_out, int out_size) {
    const float* x     = (const float*)d_in[0];
    const float* intm  = (const float*)d_in[1];
    const float* mask  = (const float*)d_in[2];
    const float* Wqkv  = (const float*)d_in[3];
    const float* bqkv  = (const float*)d_in[4];
    const float* Wproj = (const float*)d_in[5];
    const float* bproj = (const float*)d_in[6];

    float* out  = (float*)d_out;                        // [4,1024,1024]
    float* attn = out + (size_t)BB * NN_ * CC;          // [4,16,1024,1024]

    __half *xh, *wqkvh, *wprojh, *qkvh, *p, *ctxh;
    cudaGetSymbolAddress((void**)&xh,     g_xh);
    cudaGetSymbolAddress((void**)&wqkvh,  g_wqkvh);
    cudaGetSymbolAddress((void**)&wprojh, g_wprojh);
    cudaGetSymbolAddress((void**)&qkvh,   g_qkvh);
    cudaGetSymbolAddress((void**)&p,      g_p);
    cudaGetSymbolAddress((void**)&ctxh,   g_ctxh);

    // 0. converts (fp32 -> fp16)
    {
        int n4;
        n4 = M_ROWS * CC / 4;
        f2h_kernel<<<(n4 + 255) / 256, 256>>>((const float4*)x, (__half2*)xh, n4);
        n4 = CC * QKV_COLS / 4;
        f2h_kernel<<<(n4 + 255) / 256, 256>>>((const float4*)Wqkv, (__half2*)wqkvh, n4);
        n4 = CC * CC / 4;
        f2h_kernel<<<(n4 + 255) / 256, 256>>>((const float4*)Wproj, (__half2*)wprojh, n4);
    }

    // 1. qkv = x @ W_qkv + b_qkv -> fp16  (M=4096, N=3072, K=1024)
    gemm_h<128, true><<<dim3(QKV_COLS / 128, M_ROWS / 128), 256>>>(
        xh, wqkvh, bqkv, qkvh, CC, CC, QKV_COLS, QKV_COLS);

    // 2-3. fused scores (+int_matrix,+mask) + softmax -> attn fp32 + P fp16
    scores_softmax_h<<<dim3(NN_ / 32, BB * HH), 512>>>(intm, mask, attn);

    // 4. ctx = P @ V -> fp16
    ctx_h<<<dim3(1, NN_ / 128, BB * HH), 256>>>(p);

    // 5. out = ctx @ W_proj + b_proj -> fp32  (M=4096, N=1024, K=1024)
    gemm_h<128, false><<<dim3(CC / 128, M_ROWS / 128), 256>>>(
        ctxh, wprojh, bproj, out, CC, CC, CC, CC);
}

// round 8
// speedup vs baseline: 2.4129x; 1.1032x over previous
#include <cuda_runtime.h>
#include <cuda_fp16.h>
#include <stdint.h>
#include <math.h>

#define BB 4
#define NN_ 1024
#define CC 1024
#define HH 16
#define HD_ 64
#define M_ROWS (BB * NN_)        // 4096
#define QKV_COLS (3 * CC)        // 3072

// fp16 scratch (device globals: allocation-free)
__device__ __half g_xh[(size_t)M_ROWS * CC];            //  8 MB
__device__ __half g_wqkvh[(size_t)CC * QKV_COLS];       //  6 MB
__device__ __half g_wprojh[(size_t)CC * CC];            //  2 MB
__device__ __half g_qkvh[(size_t)M_ROWS * QKV_COLS];    // 24 MB
__device__ __half g_p[(size_t)BB * HH * NN_ * NN_];     // 128 MB
__device__ __half g_ctxh[(size_t)M_ROWS * CC];          //  8 MB

// ---------------------------------------------------------------------------
// helpers
// ---------------------------------------------------------------------------
__device__ __forceinline__ void mma16(float* d, const uint32_t* a,
                                      uint32_t b0, uint32_t b1) {
    asm volatile(
        "mma.sync.aligned.m16n8k16.row.col.f32.f16.f16.f32 "
        "{%0,%1,%2,%3}, {%4,%5,%6,%7}, {%8,%9}, {%0,%1,%2,%3};"
        : "+f"(d[0]), "+f"(d[1]), "+f"(d[2]), "+f"(d[3])
        : "r"(a[0]), "r"(a[1]), "r"(a[2]), "r"(a[3]), "r"(b0), "r"(b1));
}

__device__ __forceinline__ void ldmx4(uint32_t* r, const void* p) {
    uint32_t s = (uint32_t)__cvta_generic_to_shared(p);
    asm volatile("ldmatrix.sync.aligned.m8n8.x4.shared.b16 {%0,%1,%2,%3}, [%4];"
                 : "=r"(r[0]), "=r"(r[1]), "=r"(r[2]), "=r"(r[3]) : "r"(s));
}

__device__ __forceinline__ void ldmx4t(uint32_t* r, const void* p) {
    uint32_t s = (uint32_t)__cvta_generic_to_shared(p);
    asm volatile("ldmatrix.sync.aligned.m8n8.x4.trans.shared.b16 {%0,%1,%2,%3}, [%4];"
                 : "=r"(r[0]), "=r"(r[1]), "=r"(r[2]), "=r"(r[3]) : "r"(s));
}

__device__ __forceinline__ void cp16(void* smem_dst, const void* gmem_src) {
    uint32_t s = (uint32_t)__cvta_generic_to_shared(smem_dst);
    asm volatile("cp.async.cg.shared.global [%0], [%1], 16;\n" :: "r"(s), "l"(gmem_src));
}
#define CP_COMMIT() asm volatile("cp.async.commit_group;\n")
#define CP_WAIT(n)  asm volatile("cp.async.wait_group %0;\n" :: "n"(n))

// ---------------------------------------------------------------------------
// fp32 -> fp16 elementwise convert
// ---------------------------------------------------------------------------
__global__ void f2h_kernel(const float4* __restrict__ in, __half2* __restrict__ out,
                           int n4) {
    int i = blockIdx.x * blockDim.x + threadIdx.x;
    if (i < n4) {
        float4 v = in[i];
        out[2 * i]     = __floats2half2_rn(v.x, v.y);
        out[2 * i + 1] = __floats2half2_rn(v.z, v.w);
    }
}

// ---------------------------------------------------------------------------
// fp16 GEMM: C[M,N] = A[M,K] @ B[K,N] (+ bias). Block 128x128, BK=32,
// 256 threads, 3-stage cp.async, ldmatrix fragments, fp32 accum.
// Dynamic smem: As[3][128][40] | Bs[3][32][136]  = 56832 B
// ---------------------------------------------------------------------------
#define GH_SMEM (3 * 128 * 40 * 2 + 3 * 32 * 136 * 2)

template <bool OUTH>
__global__ __launch_bounds__(256) void gemm_h(
    const __half* __restrict__ A, const __half* __restrict__ B,
    const float* __restrict__ bias, void* __restrict__ Cv,
    int K, int lda, int ldb, int ldc) {

    extern __shared__ __half dsm[];
    __half (*As)[128][40]  = (__half (*)[128][40])dsm;
    __half (*Bs)[32][136]  = (__half (*)[32][136])(dsm + 3 * 128 * 40);

    const int tid  = threadIdx.x;
    const int lane = tid & 31;
    const int w    = tid >> 5;
    const int wm   = w & 3;            // 4 warps in m
    const int wn   = w >> 2;           // 2 warps in n
    const int row0 = blockIdx.y * 128;
    const int col0 = blockIdx.x * 128;
    const int m_base = wm * 32;
    const int n_base = wn * 64;
    const int lr = lane >> 2;
    const int lc = lane & 3;
    const int l15  = lane & 15;
    const int lhi8 = (lane >> 4) << 3;

    float acc[2][8][4];
#pragma unroll
    for (int i = 0; i < 2; i++)
#pragma unroll
        for (int j = 0; j < 8; j++)
#pragma unroll
            for (int t = 0; t < 4; t++) acc[i][j][t] = 0.0f;

    auto load_stage = [&](int t, int s) {
#pragma unroll
        for (int it = 0; it < 2; it++) {                 // A: 128x32 halves
            int i = tid + it * 256;
            int r = i >> 2, seg = (i & 3) * 8;
            cp16(&As[s][r][seg], &A[(size_t)(row0 + r) * lda + t * 32 + seg]);
        }
#pragma unroll
        for (int it = 0; it < 2; it++) {                 // B: 32x128 halves
            int i = tid + it * 256;
            int kk = i >> 4, nq = (i & 15) * 8;
            cp16(&Bs[s][kk][nq], &B[(size_t)(t * 32 + kk) * ldb + col0 + nq]);
        }
    };

    const int nk = K / 32;
    load_stage(0, 0);
    CP_COMMIT();
    load_stage(1, 1);
    CP_COMMIT();

    for (int t = 0; t < nk; t++) {
        if (t + 1 < nk) { CP_WAIT(1); } else { CP_WAIT(0); }
        __syncthreads();
        if (t + 2 < nk) {
            load_stage(t + 2, (t + 2) % 3);
            CP_COMMIT();
        }
        const int s = t % 3;

#pragma unroll
        for (int kst = 0; kst < 32; kst += 16) {
            uint32_t a[2][4], bfr[4][4];
#pragma unroll
            for (int mt = 0; mt < 2; mt++)
                ldmx4(a[mt], &As[s][m_base + mt * 16 + l15][kst + lhi8]);
#pragma unroll
            for (int nt = 0; nt < 4; nt++)
                ldmx4t(bfr[nt], &Bs[s][kst + l15][n_base + nt * 16 + lhi8]);
#pragma unroll
            for (int mt = 0; mt < 2; mt++)
#pragma unroll
                for (int nt = 0; nt < 4; nt++) {
                    mma16(acc[mt][2 * nt],     a[mt], bfr[nt][0], bfr[nt][1]);
                    mma16(acc[mt][2 * nt + 1], a[mt], bfr[nt][2], bfr[nt][3]);
                }
        }
        __syncthreads();
    }

    // epilogue
#pragma unroll
    for (int mt = 0; mt < 2; mt++) {
#pragma unroll
        for (int in = 0; in < 8; in++) {
            int r0 = row0 + m_base + mt * 16 + lr;
            int c0 = col0 + n_base + in * 8 + lc * 2;
            float b0 = bias ? bias[c0] : 0.0f;
            float b1 = bias ? bias[c0 + 1] : 0.0f;
            if (OUTH) {
                __half* C = (__half*)Cv;
                *(__half2*)&C[(size_t)r0 * ldc + c0] =
                    __floats2half2_rn(acc[mt][in][0] + b0, acc[mt][in][1] + b1);
                *(__half2*)&C[(size_t)(r0 + 8) * ldc + c0] =
                    __floats2half2_rn(acc[mt][in][2] + b0, acc[mt][in][3] + b1);
            } else {
                float* C = (float*)Cv;
                C[(size_t)r0 * ldc + c0]           = acc[mt][in][0] + b0;
                C[(size_t)r0 * ldc + c0 + 1]       = acc[mt][in][1] + b1;
                C[(size_t)(r0 + 8) * ldc + c0]     = acc[mt][in][2] + b0;
                C[(size_t)(r0 + 8) * ldc + c0 + 1] = acc[mt][in][3] + b1;
            }
        }
    }
}

// ---------------------------------------------------------------------------
// ctx = P @ V per (b,h). Block 128x64, BK=32, 256 thr (8 warps, 16x64 each),
// 3-stage cp.async. P fp16, V fp16 inside g_qkvh. Out fp16 g_ctxh.
// ---------------------------------------------------------------------------
__global__ __launch_bounds__(256) void ctx_h(const __half* __restrict__ P) {
    __shared__ __half As[3][128][40];
    __shared__ __half Bs[3][32][72];

    const int tid  = threadIdx.x;
    const int lane = tid & 31;
    const int w    = tid >> 5;
    const int bh = blockIdx.z;
    const int b  = bh >> 4;
    const int h  = bh & 15;
    const __half* A = P + (size_t)bh * NN_ * NN_;
    const __half* V = g_qkvh + (size_t)b * NN_ * QKV_COLS + 2 * CC + h * HD_;
    __half* Ch = g_ctxh + (size_t)b * NN_ * CC + h * HD_;

    const int row0 = blockIdx.y * 128;
    const int m_base = w * 16;
    const int lr = lane >> 2;
    const int lc = lane & 3;
    const int l15  = lane & 15;
    const int lhi8 = (lane >> 4) << 3;

    float acc[8][4];
#pragma unroll
    for (int j = 0; j < 8; j++)
#pragma unroll
        for (int t = 0; t < 4; t++) acc[j][t] = 0.0f;

    auto load_stage = [&](int t, int s) {
#pragma unroll
        for (int it = 0; it < 2; it++) {                 // P: 128x32 halves
            int i = tid + it * 256;
            int r = i >> 2, seg = (i & 3) * 8;
            cp16(&As[s][r][seg], &A[(size_t)(row0 + r) * NN_ + t * 32 + seg]);
        }
        {                                                // V: 32x64 halves
            int kk = tid >> 3, nq = (tid & 7) * 8;
            cp16(&Bs[s][kk][nq], &V[(size_t)(t * 32 + kk) * QKV_COLS + nq]);
        }
    };

    load_stage(0, 0);
    CP_COMMIT();
    load_stage(1, 1);
    CP_COMMIT();

    for (int t = 0; t < 32; t++) {
        if (t + 1 < 32) { CP_WAIT(1); } else { CP_WAIT(0); }
        __syncthreads();
        if (t + 2 < 32) {
            load_stage(t + 2, (t + 2) % 3);
            CP_COMMIT();
        }
        const int s = t % 3;

#pragma unroll
        for (int kst = 0; kst < 32; kst += 16) {
            uint32_t a[4], bfr[4][4];
            ldmx4(a, &As[s][m_base + l15][kst + lhi8]);
#pragma unroll
            for (int nt = 0; nt < 4; nt++)
                ldmx4t(bfr[nt], &Bs[s][kst + l15][nt * 16 + lhi8]);
#pragma unroll
            for (int nt = 0; nt < 4; nt++) {
                mma16(acc[2 * nt],     a, bfr[nt][0], bfr[nt][1]);
                mma16(acc[2 * nt + 1], a, bfr[nt][2], bfr[nt][3]);
            }
        }
        __syncthreads();
    }

#pragma unroll
    for (int in = 0; in < 8; in++) {
        int r0 = row0 + m_base + lr;
        int c0 = in * 8 + lc * 2;
        *(__half2*)&Ch[(size_t)r0 * CC + c0] =
            __floats2half2_rn(acc[in][0], acc[in][1]);
        *(__half2*)&Ch[(size_t)(r0 + 8) * CC + c0] =
            __floats2half2_rn(acc[in][2], acc[in][3]);
    }
}

// ---------------------------------------------------------------------------
// Fused scores + softmax (fp16 MMA). CTA = 32 rows x 1024 keys, one (b,h).
// 512 threads = 16 warps. Q frags hoisted; K streamed via cp.async 2-stage.
// Streaming hints: __ldcs on int_matrix, __stcs on attn & P writes.
// ---------------------------------------------------------------------------
__global__ __launch_bounds__(512) void scores_softmax_h(
    const float* __restrict__ intm, const float* __restrict__ mask,
    float* __restrict__ attn) {

    __shared__ __half Qs[32][72];
    __shared__ __half Ks[2][128][72];
    __shared__ float red[32][8];
    __shared__ float rowv[32];

    const int tid  = threadIdx.x;
    const int lane = tid & 31;
    const int w    = tid >> 5;
    const int lr   = lane >> 2;
    const int lc   = lane & 3;
    const int wm   = w & 1;
    const int wn   = w >> 1;
    const int l15  = lane & 15;
    const int lhi8 = (lane >> 4) << 3;
    const int bh = blockIdx.y;
    const int b  = bh >> 4;
    const int h  = bh & 15;
    const int n0 = blockIdx.x * 32;

    const __half* Q  = g_qkvh + (size_t)b * NN_ * QKV_COLS + h * HD_;
    const __half* Kp = Q + CC;

    // load Q[32][64] halves (256 x 16B)
    if (tid < 256) {
        int r = tid >> 3, seg = (tid & 7) * 8;
        *(uint4*)&Qs[r][seg] = *(const uint4*)&Q[(size_t)(n0 + r) * QKV_COLS + seg];
    }

    auto load_chunk = [&](int c, int s) {
#pragma unroll
        for (int it = 0; it < 2; it++) {                 // 128 keys x 64 halves
            int i = tid + it * 512;
            int key = i >> 3, seg = (i & 7) * 8;
            cp16(&Ks[s][key][seg], &Kp[(size_t)(c * 128 + key) * QKV_COLS + seg]);
        }
    };

    load_chunk(0, 0);
    CP_COMMIT();
    __syncthreads();

    // hoist Q fragments (4 k16 steps)
    const int qbase = wm * 16;
    uint32_t aQ[4][4];
#pragma unroll
    for (int ks = 0; ks < 4; ks++)
        ldmx4(aQ[ks], &Qs[qbase + l15][ks * 16 + lhi8]);

    float sreg[8][2][4];
#pragma unroll
    for (int c = 0; c < 8; c++)
#pragma unroll
        for (int in = 0; in < 2; in++)
#pragma unroll
            for (int t = 0; t < 4; t++) sreg[c][in][t] = 0.0f;

    for (int c = 0; c < 8; c++) {
        if (c + 1 < 8) {
            load_chunk(c + 1, (c + 1) & 1);
            CP_COMMIT();
            CP_WAIT(1);
        } else {
            CP_WAIT(0);
        }
        __syncthreads();
        const int s = c & 1;

#pragma unroll
        for (int ks = 0; ks < 4; ks++) {
            uint32_t bfr[4];
            ldmx4(bfr, &Ks[s][wn * 16 + l15][ks * 16 + lhi8]);
            mma16(sreg[c][0], aQ[ks], bfr[0], bfr[2]);
            mma16(sreg[c][1], aQ[ks], bfr[1], bfr[3]);
        }

        // epilogue: scale + int_matrix (streamed) + mask
#pragma unroll
        for (int in = 0; in < 2; in++) {
#pragma unroll
            for (int hh = 0; hh < 2; hh++) {
                int r   = qbase + lr + hh * 8;
                int key = c * 128 + wn * 16 + in * 8 + lc * 2;
                size_t aidx = ((size_t)bh * NN_ + n0 + r) * NN_ + key;
                size_t midx = ((size_t)b  * NN_ + n0 + r) * NN_ + key;
                float2 iv = __ldcs((const float2*)&intm[aidx]);
                float2 mv = *(const float2*)&mask[midx];
                sreg[c][in][hh * 2]     = 0.125f * sreg[c][in][hh * 2]     + iv.x
                                          + (1.0f - mv.x) * (-1e9f);
                sreg[c][in][hh * 2 + 1] = 0.125f * sreg[c][in][hh * 2 + 1] + iv.y
                                          + (1.0f - mv.y) * (-1e9f);
            }
        }
        __syncthreads();
    }

    // ---- softmax over registers (rows qbase+lr, qbase+8+lr)
    float mx[2] = {-1e30f, -1e30f};
#pragma unroll
    for (int c = 0; c < 8; c++)
#pragma unroll
        for (int in = 0; in < 2; in++)
#pragma unroll
            for (int hh = 0; hh < 2; hh++)
                mx[hh] = fmaxf(mx[hh],
                               fmaxf(sreg[c][in][hh * 2], sreg[c][in][hh * 2 + 1]));
#pragma unroll
    for (int hh = 0; hh < 2; hh++) {
        mx[hh] = fmaxf(mx[hh], __shfl_xor_sync(0xffffffffu, mx[hh], 1));
        mx[hh] = fmaxf(mx[hh], __shfl_xor_sync(0xffffffffu, mx[hh], 2));
    }
    if (lc == 0) {
        red[qbase + lr][wn]     = mx[0];
        red[qbase + 8 + lr][wn] = mx[1];
    }
    __syncthreads();
    if (tid < 32) {
        float m = red[tid][0];
#pragma unroll
        for (int j = 1; j < 8; j++) m = fmaxf(m, red[tid][j]);
        rowv[tid] = m;
    }
    __syncthreads();
    float rmx[2] = {rowv[qbase + lr], rowv[qbase + 8 + lr]};
    __syncthreads();

    float sum[2] = {0.0f, 0.0f};
#pragma unroll
    for (int c = 0; c < 8; c++)
#pragma unroll
        for (int in = 0; in < 2; in++)
#pragma unroll
            for (int hh = 0; hh < 2; hh++) {
                float e0 = __expf(sreg[c][in][hh * 2]     - rmx[hh]);
                float e1 = __expf(sreg[c][in][hh * 2 + 1] - rmx[hh]);
                sreg[c][in][hh * 2]     = e0;
                sreg[c][in][hh * 2 + 1] = e1;
                sum[hh] += e0 + e1;
            }
#pragma unroll
    for (int hh = 0; hh < 2; hh++) {
        sum[hh] += __shfl_xor_sync(0xffffffffu, sum[hh], 1);
        sum[hh] += __shfl_xor_sync(0xffffffffu, sum[hh], 2);
    }
    if (lc == 0) {
        red[qbase + lr][wn]     = sum[0];
        red[qbase + 8 + lr][wn] = sum[1];
    }
    __syncthreads();
    if (tid < 32) {
        float s = 0.0f;
#pragma unroll
        for (int j = 0; j < 8; j++) s += red[tid][j];
        rowv[tid] = 1.0f / s;
    }
    __syncthreads();
    float inv[2] = {rowv[qbase + lr], rowv[qbase + 8 + lr]};

    // ---- write attn (fp32 output, streamed) and P (fp16 for ctx, streamed)
#pragma unroll
    for (int c = 0; c < 8; c++)
#pragma unroll
        for (int in = 0; in < 2; in++)
#pragma unroll
            for (int hh = 0; hh < 2; hh++) {
                int r   = qbase + lr + hh * 8;
                int key = c * 128 + wn * 16 + in * 8 + lc * 2;
                size_t aidx = ((size_t)bh * NN_ + n0 + r) * NN_ + key;
                float2 e;
                e.x = sreg[c][in][hh * 2] * inv[hh];
                e.y = sreg[c][in][hh * 2 + 1] * inv[hh];
                __stcs((float2*)&attn[aidx], e);
                __half2 ph = __floats2half2_rn(e.x, e.y);
                __stcs((__half2*)&g_p[aidx], ph);
            }
}

// ---------------------------------------------------------------------------
extern "C" void kernel_launch(void* const* d_in, const int* in_sizes, int n_in,
                              void* d_out, int out_size) {
    const float* x     = (const float*)d_in[0];
    const float* intm  = (const float*)d_in[1];
    const float* mask  = (const float*)d_in[2];
    const float* Wqkv  = (const float*)d_in[3];
    const float* bqkv  = (const float*)d_in[4];
    const float* Wproj = (const float*)d_in[5];
    const float* bproj = (const float*)d_in[6];

    float* out  = (float*)d_out;                        // [4,1024,1024]
    float* attn = out + (size_t)BB * NN_ * CC;          // [4,16,1024,1024]

    __half *xh, *wqkvh, *wprojh, *qkvh, *p, *ctxh;
    cudaGetSymbolAddress((void**)&xh,     g_xh);
    cudaGetSymbolAddress((void**)&wqkvh,  g_wqkvh);
    cudaGetSymbolAddress((void**)&wprojh, g_wprojh);
    cudaGetSymbolAddress((void**)&qkvh,   g_qkvh);
    cudaGetSymbolAddress((void**)&p,      g_p);
    cudaGetSymbolAddress((void**)&ctxh,   g_ctxh);

    cudaFuncSetAttribute(gemm_h<true>,
                         cudaFuncAttributeMaxDynamicSharedMemorySize, GH_SMEM);
    cudaFuncSetAttribute(gemm_h<false>,
                         cudaFuncAttributeMaxDynamicSharedMemorySize, GH_SMEM);

    // 0. converts (fp32 -> fp16)
    {
        int n4;
        n4 = M_ROWS * CC / 4;
        f2h_kernel<<<(n4 + 255) / 256, 256>>>((const float4*)x, (__half2*)xh, n4);
        n4 = CC * QKV_COLS / 4;
        f2h_kernel<<<(n4 + 255) / 256, 256>>>((const float4*)Wqkv, (__half2*)wqkvh, n4);
        n4 = CC * CC / 4;
        f2h_kernel<<<(n4 + 255) / 256, 256>>>((const float4*)Wproj, (__half2*)wprojh, n4);
    }

    // 1. qkv = x @ W_qkv + b_qkv -> fp16  (M=4096, N=3072, K=1024)
    gemm_h<true><<<dim3(QKV_COLS / 128, M_ROWS / 128), 256, GH_SMEM>>>(
        xh, wqkvh, bqkv, qkvh, CC, CC, QKV_COLS, QKV_COLS);

    // 2-3. fused scores (+int_matrix,+mask) + softmax -> attn fp32 + P fp16
    scores_softmax_h<<<dim3(NN_ / 32, BB * HH), 512>>>(intm, mask, attn);

    // 4. ctx = P @ V -> fp16
    ctx_h<<<dim3(1, NN_ / 128, BB * HH), 256>>>(p);

    // 5. out = ctx @ W_proj + b_proj -> fp32  (M=4096, N=1024, K=1024)
    gemm_h<false><<<dim3(CC / 128, M_ROWS / 128), 256, GH_SMEM>>>(
        ctxh, wprojh, bproj, out, CC, CC, CC, CC);
}

// round 11
// speedup vs baseline: 2.6664x; 1.1050x over previous
#include <cuda_runtime.h>
#include <cuda_fp16.h>
#include <stdint.h>
#include <string.h>
#include <math.h>

#define BB 4
#define NN_ 1024
#define CC 1024
#define HH 16
#define HD_ 64
#define M_ROWS (BB * NN_)        // 4096
#define QKV_COLS (3 * CC)        // 3072

// fp16 scratch (device globals: allocation-free)
__device__ __half g_xh[(size_t)M_ROWS * CC];            //  8 MB
__device__ __half g_wqkvh[(size_t)CC * QKV_COLS];       //  6 MB
__device__ __half g_wprojh[(size_t)CC * CC];            //  2 MB
__device__ __half g_qkvh[(size_t)M_ROWS * QKV_COLS];    // 24 MB
__device__ __half g_ctxh[(size_t)M_ROWS * CC];          //  8 MB

// ---------------------------------------------------------------------------
// helpers
// ---------------------------------------------------------------------------
__device__ __forceinline__ uint32_t h2_bits(__half2 h) {
    uint32_t u;
    memcpy(&u, &h, 4);
    return u;
}

__device__ __forceinline__ void mma16(float* d, const uint32_t* a,
                                      uint32_t b0, uint32_t b1) {
    asm volatile(
        "mma.sync.aligned.m16n8k16.row.col.f32.f16.f16.f32 "
        "{%0,%1,%2,%3}, {%4,%5,%6,%7}, {%8,%9}, {%0,%1,%2,%3};"
        : "+f"(d[0]), "+f"(d[1]), "+f"(d[2]), "+f"(d[3])
        : "r"(a[0]), "r"(a[1]), "r"(a[2]), "r"(a[3]), "r"(b0), "r"(b1));
}

__device__ __forceinline__ void ldmx4(uint32_t* r, const void* p) {
    uint32_t s = (uint32_t)__cvta_generic_to_shared(p);
    asm volatile("ldmatrix.sync.aligned.m8n8.x4.shared.b16 {%0,%1,%2,%3}, [%4];"
                 : "=r"(r[0]), "=r"(r[1]), "=r"(r[2]), "=r"(r[3]) : "r"(s));
}

__device__ __forceinline__ void ldmx4t(uint32_t* r, const void* p) {
    uint32_t s = (uint32_t)__cvta_generic_to_shared(p);
    asm volatile("ldmatrix.sync.aligned.m8n8.x4.trans.shared.b16 {%0,%1,%2,%3}, [%4];"
                 : "=r"(r[0]), "=r"(r[1]), "=r"(r[2]), "=r"(r[3]) : "r"(s));
}

__device__ __forceinline__ void cp16(void* smem_dst, const void* gmem_src) {
    uint32_t s = (uint32_t)__cvta_generic_to_shared(smem_dst);
    asm volatile("cp.async.cg.shared.global [%0], [%1], 16;\n" :: "r"(s), "l"(gmem_src));
}
#define CP_COMMIT() asm volatile("cp.async.commit_group;\n")
#define CP_WAIT(n)  asm volatile("cp.async.wait_group %0;\n" :: "n"(n))

// ---------------------------------------------------------------------------
// fp32 -> fp16 elementwise convert
// ---------------------------------------------------------------------------
__global__ void f2h_kernel(const float4* __restrict__ in, __half2* __restrict__ out,
                           int n4) {
    int i = blockIdx.x * blockDim.x + threadIdx.x;
    if (i < n4) {
        float4 v = in[i];
        out[2 * i]     = __floats2half2_rn(v.x, v.y);
        out[2 * i + 1] = __floats2half2_rn(v.z, v.w);
    }
}

// ---------------------------------------------------------------------------
// fp16 GEMM: C[M,N] = A[M,K] @ B[K,N] (+ bias). Block 128x128, BK=64,
// 256 threads, 2-stage cp.async, ldmatrix fragments, fp32 accum.
// Dynamic smem: As[2][128][72] | Bs[2][64][136] = 71680 B
// ---------------------------------------------------------------------------
#define GH_SMEM ((2 * 128 * 72 + 2 * 64 * 136) * 2)

template <bool OUTH>
__global__ __launch_bounds__(256) void gemm_h(
    const __half* __restrict__ A, const __half* __restrict__ B,
    const float* __restrict__ bias, void* __restrict__ Cv,
    int K, int lda, int ldb, int ldc) {

    extern __shared__ __half dsm[];
    __half (*As)[128][72] = (__half (*)[128][72])dsm;
    __half (*Bs)[64][136] = (__half (*)[64][136])(dsm + 2 * 128 * 72);

    const int tid  = threadIdx.x;
    const int lane = tid & 31;
    const int w    = tid >> 5;
    const int wm   = w & 3;
    const int wn   = w >> 2;
    const int row0 = blockIdx.y * 128;
    const int col0 = blockIdx.x * 128;
    const int m_base = wm * 32;
    const int n_base = wn * 64;
    const int lr = lane >> 2;
    const int lc = lane & 3;
    const int l15  = lane & 15;
    const int lhi8 = (lane >> 4) << 3;

    float acc[2][8][4];
#pragma unroll
    for (int i = 0; i < 2; i++)
#pragma unroll
        for (int j = 0; j < 8; j++)
#pragma unroll
            for (int t = 0; t < 4; t++) acc[i][j][t] = 0.0f;

    auto load_stage = [&](int t, int s) {
#pragma unroll
        for (int it = 0; it < 4; it++) {                 // A: 128 x 64 halves
            int i = tid + it * 256;
            int r = i >> 3, seg = (i & 7) * 8;
            cp16(&As[s][r][seg], &A[(size_t)(row0 + r) * lda + t * 64 + seg]);
        }
#pragma unroll
        for (int it = 0; it < 4; it++) {                 // B: 64 x 128 halves
            int i = tid + it * 256;
            int kk = i >> 4, nq = (i & 15) * 8;
            cp16(&Bs[s][kk][nq], &B[(size_t)(t * 64 + kk) * ldb + col0 + nq]);
        }
    };

    const int nk = K / 64;
    load_stage(0, 0);
    CP_COMMIT();
    load_stage(1, 1);
    CP_COMMIT();

    for (int t = 0; t < nk; t++) {
        if (t + 1 < nk) { CP_WAIT(1); } else { CP_WAIT(0); }
        __syncthreads();
        const int s = t & 1;

#pragma unroll
        for (int kst = 0; kst < 64; kst += 16) {
            uint32_t a[2][4], bfr[4][4];
#pragma unroll
            for (int mt = 0; mt < 2; mt++)
                ldmx4(a[mt], &As[s][m_base + mt * 16 + l15][kst + lhi8]);
#pragma unroll
            for (int nt = 0; nt < 4; nt++)
                ldmx4t(bfr[nt], &Bs[s][kst + l15][n_base + nt * 16 + lhi8]);
#pragma unroll
            for (int mt = 0; mt < 2; mt++)
#pragma unroll
                for (int nt = 0; nt < 4; nt++) {
                    mma16(acc[mt][2 * nt],     a[mt], bfr[nt][0], bfr[nt][1]);
                    mma16(acc[mt][2 * nt + 1], a[mt], bfr[nt][2], bfr[nt][3]);
                }
        }
        __syncthreads();
        if (t + 2 < nk) {
            load_stage(t + 2, s);
            CP_COMMIT();
        }
    }

    // epilogue
#pragma unroll
    for (int mt = 0; mt < 2; mt++) {
#pragma unroll
        for (int in = 0; in < 8; in++) {
            int r0 = row0 + m_base + mt * 16 + lr;
            int c0 = col0 + n_base + in * 8 + lc * 2;
            float b0 = bias ? bias[c0] : 0.0f;
            float b1 = bias ? bias[c0 + 1] : 0.0f;
            if (OUTH) {
                __half* C = (__half*)Cv;
                *(__half2*)&C[(size_t)r0 * ldc + c0] =
                    __floats2half2_rn(acc[mt][in][0] + b0, acc[mt][in][1] + b1);
                *(__half2*)&C[(size_t)(r0 + 8) * ldc + c0] =
                    __floats2half2_rn(acc[mt][in][2] + b0, acc[mt][in][3] + b1);
            } else {
                float* C = (float*)Cv;
                C[(size_t)r0 * ldc + c0]           = acc[mt][in][0] + b0;
                C[(size_t)r0 * ldc + c0 + 1]       = acc[mt][in][1] + b1;
                C[(size_t)(r0 + 8) * ldc + c0]     = acc[mt][in][2] + b0;
                C[(size_t)(r0 + 8) * ldc + c0 + 1] = acc[mt][in][3] + b1;
            }
        }
    }
}

// ---------------------------------------------------------------------------
// Fused scores + softmax + P@V. CTA = 32 rows x 1024 keys, one (b,h).
// 512 threads = 16 warps (wm = w&1 rows, wn = w>>1 keys-within-chunk).
// Scores in regs -> softmax -> attn write; P@V via direct register->A-fragment
// reuse (8-way split-K across wn) with V streamed through the K smem buffers,
// then smem split-K reduction -> g_ctxh.
// Dynamic smem layout (bytes):
//   [0,     4608)   Qs[32][72] fp16
//   [4608, 70144)   union: Ks/Vs[2][128][72] fp16 (36864) | redbuf[16][1024] f32
//   [70144,71168)   red[32][8] f32
//   [71168,71296)   rowv[32] f32
// ---------------------------------------------------------------------------
#define FA_UNION 4608
#define FA_RED   70144
#define FA_ROWV  71168
#define FA_SMEM  71296

__global__ __launch_bounds__(512) void scores_softmax_pv(
    const float* __restrict__ intm, const float* __restrict__ mask,
    float* __restrict__ attn) {

    extern __shared__ char sm[];
    __half (*Qs)[72]       = (__half (*)[72])sm;
    __half (*Ks)[128][72]  = (__half (*)[128][72])(sm + FA_UNION);
    float*  redbuf         = (float*)(sm + FA_UNION);
    float (*red)[8]        = (float (*)[8])(sm + FA_RED);
    float*  rowv           = (float*)(sm + FA_ROWV);

    const int tid  = threadIdx.x;
    const int lane = tid & 31;
    const int w    = tid >> 5;
    const int lr   = lane >> 2;
    const int lc   = lane & 3;
    const int wm   = w & 1;
    const int wn   = w >> 1;
    const int l15  = lane & 15;
    const int lhi8 = (lane >> 4) << 3;
    const int bh = blockIdx.y;
    const int b  = bh >> 4;
    const int h  = bh & 15;
    const int n0 = blockIdx.x * 32;

    const __half* Q  = g_qkvh + (size_t)b * NN_ * QKV_COLS + h * HD_;
    const __half* Kp = Q + CC;
    const __half* Vp = Q + 2 * CC;

    // load Q[32][64] halves (256 x 16B)
    if (tid < 256) {
        int r = tid >> 3, seg = (tid & 7) * 8;
        *(uint4*)&Qs[r][seg] = *(const uint4*)&Q[(size_t)(n0 + r) * QKV_COLS + seg];
    }

    auto load_tile = [&](const __half* base, int c, int s) {
#pragma unroll
        for (int it = 0; it < 2; it++) {                 // 128 rows x 64 halves
            int i = tid + it * 512;
            int key = i >> 3, seg = (i & 7) * 8;
            cp16(&Ks[s][key][seg], &base[(size_t)(c * 128 + key) * QKV_COLS + seg]);
        }
    };

    load_tile(Kp, 0, 0);
    CP_COMMIT();
    __syncthreads();

    // hoist Q fragments (4 k16 steps)
    const int qbase = wm * 16;
    uint32_t aQ[4][4];
#pragma unroll
    for (int ks = 0; ks < 4; ks++)
        ldmx4(aQ[ks], &Qs[qbase + l15][ks * 16 + lhi8]);

    float sreg[8][2][4];
#pragma unroll
    for (int c = 0; c < 8; c++)
#pragma unroll
        for (int in = 0; in < 2; in++)
#pragma unroll
            for (int t = 0; t < 4; t++) sreg[c][in][t] = 0.0f;

    // ---- scores: 8 chunks of 128 keys
    for (int c = 0; c < 8; c++) {
        if (c + 1 < 8) {
            load_tile(Kp, c + 1, (c + 1) & 1);
            CP_COMMIT();
            CP_WAIT(1);
        } else {
            CP_WAIT(0);
        }
        __syncthreads();
        const int s = c & 1;

#pragma unroll
        for (int ks = 0; ks < 4; ks++) {
            uint32_t bfr[4];
            ldmx4(bfr, &Ks[s][wn * 16 + l15][ks * 16 + lhi8]);
            mma16(sreg[c][0], aQ[ks], bfr[0], bfr[2]);
            mma16(sreg[c][1], aQ[ks], bfr[1], bfr[3]);
        }

        // epilogue: scale + int_matrix (streamed) + mask
#pragma unroll
        for (int in = 0; in < 2; in++) {
#pragma unroll
            for (int hh = 0; hh < 2; hh++) {
                int r   = qbase + lr + hh * 8;
                int key = c * 128 + wn * 16 + in * 8 + lc * 2;
                size_t aidx = ((size_t)bh * NN_ + n0 + r) * NN_ + key;
                size_t midx = ((size_t)b  * NN_ + n0 + r) * NN_ + key;
                float2 iv = __ldcs((const float2*)&intm[aidx]);
                float2 mv = *(const float2*)&mask[midx];
                sreg[c][in][hh * 2]     = 0.125f * sreg[c][in][hh * 2]     + iv.x
                                          + (1.0f - mv.x) * (-1e9f);
                sreg[c][in][hh * 2 + 1] = 0.125f * sreg[c][in][hh * 2 + 1] + iv.y
                                          + (1.0f - mv.y) * (-1e9f);
            }
        }
        __syncthreads();
    }

    // preload V chunks 0,1 into the (now dead) K buffers; softmax hides latency
    load_tile(Vp, 0, 0);
    CP_COMMIT();
    load_tile(Vp, 1, 1);
    CP_COMMIT();

    // ---- softmax over registers (rows qbase+lr, qbase+8+lr)
    float mx[2] = {-1e30f, -1e30f};
#pragma unroll
    for (int c = 0; c < 8; c++)
#pragma unroll
        for (int in = 0; in < 2; in++)
#pragma unroll
            for (int hh = 0; hh < 2; hh++)
                mx[hh] = fmaxf(mx[hh],
                               fmaxf(sreg[c][in][hh * 2], sreg[c][in][hh * 2 + 1]));
#pragma unroll
    for (int hh = 0; hh < 2; hh++) {
        mx[hh] = fmaxf(mx[hh], __shfl_xor_sync(0xffffffffu, mx[hh], 1));
        mx[hh] = fmaxf(mx[hh], __shfl_xor_sync(0xffffffffu, mx[hh], 2));
    }
    if (lc == 0) {
        red[qbase + lr][wn]     = mx[0];
        red[qbase + 8 + lr][wn] = mx[1];
    }
    __syncthreads();
    if (tid < 32) {
        float m = red[tid][0];
#pragma unroll
        for (int j = 1; j < 8; j++) m = fmaxf(m, red[tid][j]);
        rowv[tid] = m;
    }
    __syncthreads();
    float rmx[2] = {rowv[qbase + lr], rowv[qbase + 8 + lr]};
    __syncthreads();

    float sum[2] = {0.0f, 0.0f};
#pragma unroll
    for (int c = 0; c < 8; c++)
#pragma unroll
        for (int in = 0; in < 2; in++)
#pragma unroll
            for (int hh = 0; hh < 2; hh++) {
                float e0 = __expf(sreg[c][in][hh * 2]     - rmx[hh]);
                float e1 = __expf(sreg[c][in][hh * 2 + 1] - rmx[hh]);
                sreg[c][in][hh * 2]     = e0;
                sreg[c][in][hh * 2 + 1] = e1;
                sum[hh] += e0 + e1;
            }
#pragma unroll
    for (int hh = 0; hh < 2; hh++) {
        sum[hh] += __shfl_xor_sync(0xffffffffu, sum[hh], 1);
        sum[hh] += __shfl_xor_sync(0xffffffffu, sum[hh], 2);
    }
    if (lc == 0) {
        red[qbase + lr][wn]     = sum[0];
        red[qbase + 8 + lr][wn] = sum[1];
    }
    __syncthreads();
    if (tid < 32) {
        float s = 0.0f;
#pragma unroll
        for (int j = 0; j < 8; j++) s += red[tid][j];
        rowv[tid] = 1.0f / s;
    }
    __syncthreads();
    float inv[2] = {rowv[qbase + lr], rowv[qbase + 8 + lr]};

    // ---- P@V with direct register A-fragments + attn writes, per chunk
    float cacc[8][4];
#pragma unroll
    for (int j = 0; j < 8; j++)
#pragma unroll
        for (int t = 0; t < 4; t++) cacc[j][t] = 0.0f;

    for (int c = 0; c < 8; c++) {
        // write attn for chunk c (uses regs only; overlaps V load)
        uint32_t aP[4];
        {
            float p00 = sreg[c][0][0] * inv[0], p01 = sreg[c][0][1] * inv[0];
            float p02 = sreg[c][0][2] * inv[1], p03 = sreg[c][0][3] * inv[1];
            float p10 = sreg[c][1][0] * inv[0], p11 = sreg[c][1][1] * inv[0];
            float p12 = sreg[c][1][2] * inv[1], p13 = sreg[c][1][3] * inv[1];
            int key0 = c * 128 + wn * 16 + lc * 2;
            size_t r0 = ((size_t)bh * NN_ + n0 + qbase + lr) * NN_;
            size_t r1 = ((size_t)bh * NN_ + n0 + qbase + 8 + lr) * NN_;
            __stcs((float2*)&attn[r0 + key0],     make_float2(p00, p01));
            __stcs((float2*)&attn[r1 + key0],     make_float2(p02, p03));
            __stcs((float2*)&attn[r0 + key0 + 8], make_float2(p10, p11));
            __stcs((float2*)&attn[r1 + key0 + 8], make_float2(p12, p13));
            // A-fragment for m16n8k16: k-dim = 16 keys of this warp's slice
            aP[0] = h2_bits(__floats2half2_rn(p00, p01));
            aP[1] = h2_bits(__floats2half2_rn(p02, p03));
            aP[2] = h2_bits(__floats2half2_rn(p10, p11));
            aP[3] = h2_bits(__floats2half2_rn(p12, p13));
        }

        if (c + 1 < 8) { CP_WAIT(1); } else { CP_WAIT(0); }
        __syncthreads();
        const int s = c & 1;

#pragma unroll
        for (int nt = 0; nt < 4; nt++) {
            uint32_t bfr[4];
            ldmx4t(bfr, &Ks[s][wn * 16 + l15][nt * 16 + lhi8]);
            mma16(cacc[2 * nt],     aP, bfr[0], bfr[1]);
            mma16(cacc[2 * nt + 1], aP, bfr[2], bfr[3]);
        }
        __syncthreads();
        if (c + 2 < 8) {
            load_tile(Vp, c + 2, s);
            CP_COMMIT();
        }
    }

    // ---- split-K reduction across 8 wn groups (redbuf overlays K/V smem)
#pragma unroll
    for (int in = 0; in < 8; in++) {
        int d = in * 8 + lc * 2;
        *(float2*)&redbuf[w * 1024 + lr * 64 + d] =
            make_float2(cacc[in][0], cacc[in][1]);
        *(float2*)&redbuf[w * 1024 + (lr + 8) * 64 + d] =
            make_float2(cacc[in][2], cacc[in][3]);
    }
    __syncthreads();

    __half* Ch = g_ctxh + ((size_t)b * NN_ + n0) * CC + h * HD_;
#pragma unroll
    for (int j = 0; j < 2; j++) {
        int i = tid + j * 512;          // 0..1023 : 32 rows x 32 half2
        int r  = i >> 5;
        int d2 = (i & 31) * 2;
        int rg = r >> 4, rl = r & 15;
        float s0 = 0.0f, s1 = 0.0f;
#pragma unroll
        for (int k = 0; k < 8; k++) {
            float2 v = *(const float2*)&redbuf[(k * 2 + rg) * 1024 + rl * 64 + d2];
            s0 += v.x;
            s1 += v.y;
        }
        *(__half2*)&Ch[(size_t)r * CC + d2] = __floats2half2_rn(s0, s1);
    }
}

// ---------------------------------------------------------------------------
extern "C" void kernel_launch(void* const* d_in, const int* in_sizes, int n_in,
                              void* d_out, int out_size) {
    const float* x     = (const float*)d_in[0];
    const float* intm  = (const float*)d_in[1];
    const float* mask  = (const float*)d_in[2];
    const float* Wqkv  = (const float*)d_in[3];
    const float* bqkv  = (const float*)d_in[4];
    const float* Wproj = (const float*)d_in[5];
    const float* bproj = (const float*)d_in[6];

    float* out  = (float*)d_out;                        // [4,1024,1024]
    float* attn = out + (size_t)BB * NN_ * CC;          // [4,16,1024,1024]

    __half *xh, *wqkvh, *wprojh, *qkvh, *ctxh;
    cudaGetSymbolAddress((void**)&xh,     g_xh);
    cudaGetSymbolAddress((void**)&wqkvh,  g_wqkvh);
    cudaGetSymbolAddress((void**)&wprojh, g_wprojh);
    cudaGetSymbolAddress((void**)&qkvh,   g_qkvh);
    cudaGetSymbolAddress((void**)&ctxh,   g_ctxh);

    cudaFuncSetAttribute(gemm_h<true>,
                         cudaFuncAttributeMaxDynamicSharedMemorySize, GH_SMEM);
    cudaFuncSetAttribute(gemm_h<false>,
                         cudaFuncAttributeMaxDynamicSharedMemorySize, GH_SMEM);
    cudaFuncSetAttribute(scores_softmax_pv,
                         cudaFuncAttributeMaxDynamicSharedMemorySize, FA_SMEM);

    // 0. converts (fp32 -> fp16)
    {
        int n4;
        n4 = M_ROWS * CC / 4;
        f2h_kernel<<<(n4 + 255) / 256, 256>>>((const float4*)x, (__half2*)xh, n4);
        n4 = CC * QKV_COLS / 4;
        f2h_kernel<<<(n4 + 255) / 256, 256>>>((const float4*)Wqkv, (__half2*)wqkvh, n4);
        n4 = CC * CC / 4;
        f2h_kernel<<<(n4 + 255) / 256, 256>>>((const float4*)Wproj, (__half2*)wprojh, n4);
    }

    // 1. qkv = x @ W_qkv + b_qkv -> fp16  (M=4096, N=3072, K=1024)
    gemm_h<true><<<dim3(QKV_COLS / 128, M_ROWS / 128), 256, GH_SMEM>>>(
        xh, wqkvh, bqkv, qkvh, CC, CC, QKV_COLS, QKV_COLS);

    // 2-4. fused scores (+int_matrix,+mask) + softmax + attn write + P@V -> ctx
    scores_softmax_pv<<<dim3(NN_ / 32, BB * HH), 512, FA_SMEM>>>(intm, mask, attn);

    // 5. out = ctx @ W_proj + b_proj -> fp32  (M=4096, N=1024, K=1024)
    gemm_h<false><<<dim3(CC / 128, M_ROWS / 128), 256, GH_SMEM>>>(
        ctxh, wprojh, bproj, out, CC, CC, CC, CC);
}